// round 4
// baseline (speedup 1.0000x reference)
#include <cuda_runtime.h>

#define N_NODES 50000
#define N_EDGES 800000

// Scatter-aggregation scratch + decoded edge indices
// (device globals: allocation rules forbid cudaMalloc)
__device__ float g_msg[N_NODES * 64];
__device__ float g_coord[N_NODES * 3];
__device__ int   g_row[N_EDGES];
__device__ int   g_col[N_EDGES];

__device__ __forceinline__ float silu(float x) {
    return x * (1.0f / (1.0f + __expf(-x)));
}

// ---------------------------------------------------------------------------
// Decode edge_index. The reference says int64 but JAX with x64 disabled emits
// int32 — detect at runtime. For int64 (values < 2^31, little-endian) every
// odd 32-bit word is 0; for int32 random indices that is impossible across 64
// consecutive odd words. Indices are clamped so a wrong guess can never cause
// an illegal access (it would surface as rel_err instead).
// ---------------------------------------------------------------------------
__global__ void decode_edges(const unsigned int* __restrict__ w) {
    __shared__ int is64_s;
    if (threadIdx.x == 0) {
        int is64 = 1;
        #pragma unroll 1
        for (int i = 1; i < 128; i += 2)
            if (w[i] != 0u) { is64 = 0; break; }
        is64_s = is64;
    }
    __syncthreads();
    const int is64 = is64_s;
    const int total = 2 * N_EDGES;
    for (int i = blockIdx.x * blockDim.x + threadIdx.x; i < total;
         i += gridDim.x * blockDim.x) {
        int v = is64 ? (int)w[2 * i] : (int)w[i];
        v = max(0, min(v, N_NODES - 1));
        if (i < N_EDGES) g_row[i] = v;
        else             g_col[i - N_EDGES] = v;
    }
}

// ---------------------------------------------------------------------------
// Edge kernel: warp processes 4 edges at a time.
// Lane owns output columns j0 = 2*lane, j0+1 for each of the 4 edges.
// Shared: all edge-path weights + per-warp activation scratch (528 floats).
// ---------------------------------------------------------------------------
__global__ __launch_bounds__(256, 2) void edge_kernel(
    const float* __restrict__ h, const float* __restrict__ pos,
    const float* __restrict__ We1, const float* __restrict__ be1,
    const float* __restrict__ We2, const float* __restrict__ be2,
    const float* __restrict__ Wc1, const float* __restrict__ bc1,
    const float* __restrict__ Wc2, const float* __restrict__ bc2)
{
    extern __shared__ float sm[];
    float* We1s = sm;                    // 129*64 = 8256
    float* We2s = We1s + 129 * 64;       // 4096
    float* Wc1s = We2s + 64 * 64;        // 4096
    float* be1s = Wc1s + 64 * 64;        // 64
    float* be2s = be1s + 64;             // 64
    float* bc1s = be2s + 64;             // 64
    float* Wc2s = bc1s + 64;             // 64
    float* scrA = Wc2s + 64;             // 8*528 per-warp scratch
    float* rels = scrA + 8 * 528;        // 8*12
    int*   rowsS = (int*)(rels + 96);    // 8*4
    int*   colsS = rowsS + 32;           // 8*4

    const int tid = threadIdx.x;
    for (int i = tid; i < 129 * 64; i += 256) We1s[i] = We1[i];
    for (int i = tid; i < 64 * 64; i += 256) { We2s[i] = We2[i]; Wc1s[i] = Wc1[i]; }
    if (tid < 64) {
        be1s[tid] = be1[tid]; be2s[tid] = be2[tid];
        bc1s[tid] = bc1[tid]; Wc2s[tid] = Wc2[tid];
    }
    __syncthreads();

    const float bc2v = __ldg(bc2);
    const int lane = tid & 31;
    const int w = tid >> 5;
    const int j0 = lane * 2;
    float* X  = scrA + w * 528;
    float* rl = rels + w * 12;
    int*   rw = rowsS + w * 4;
    int*   cl = colsS + w * 4;

    const int nTiles = N_EDGES / 4;        // 200000
    const int warpStride = gridDim.x * 8;

    for (int t = blockIdx.x * 8 + w; t < nTiles; t += warpStride) {
        __syncwarp();   // protect rw/cl/X from previous iteration's readers
        const int base = t * 4;
        if (lane < 4) {
            rw[lane] = g_row[base + lane];
            cl[lane] = g_col[base + lane];
        }
        __syncwarp();

        // ---- stage edge inputs x = [h[row] | h[col] | dist_sq] into scratch
        #pragma unroll
        for (int e = 0; e < 4; e++) {
            const int r = rw[e], c = cl[e];
            float2 a = ((const float2*)(h + (size_t)r * 64))[lane];
            float2 b = ((const float2*)(h + (size_t)c * 64))[lane];
            ((float2*)(X + e * 132))[lane] = a;
            ((float2*)(X + e * 132 + 64))[lane] = b;
        }
        if (lane < 4) {
            const int e = lane;
            const int r = rw[e], c = cl[e];
            float dx = pos[r * 3 + 0] - pos[c * 3 + 0];
            float dy = pos[r * 3 + 1] - pos[c * 3 + 1];
            float dz = pos[r * 3 + 2] - pos[c * 3 + 2];
            rl[e * 3 + 0] = dx; rl[e * 3 + 1] = dy; rl[e * 3 + 2] = dz;
            X[e * 132 + 128] = dx * dx + dy * dy + dz * dz;
        }
        __syncwarp();

        // ---- edge MLP layer 1: (129 -> 64), SiLU
        float acc[4][2];
        {
            float b0 = be1s[j0], b1 = be1s[j0 + 1];
            #pragma unroll
            for (int e = 0; e < 4; e++) { acc[e][0] = b0; acc[e][1] = b1; }
        }
        #pragma unroll 2
        for (int k = 0; k < 128; k += 4) {
            float xv[4][4];
            #pragma unroll
            for (int e = 0; e < 4; e++) {
                float4 q = *(const float4*)(X + e * 132 + k);
                xv[e][0] = q.x; xv[e][1] = q.y; xv[e][2] = q.z; xv[e][3] = q.w;
            }
            #pragma unroll
            for (int kk = 0; kk < 4; kk++) {
                float2 wv = *(const float2*)(We1s + (k + kk) * 64 + j0);
                #pragma unroll
                for (int e = 0; e < 4; e++) {
                    acc[e][0] = fmaf(xv[e][kk], wv.x, acc[e][0]);
                    acc[e][1] = fmaf(xv[e][kk], wv.y, acc[e][1]);
                }
            }
        }
        {
            float2 wv = *(const float2*)(We1s + 128 * 64 + j0);
            #pragma unroll
            for (int e = 0; e < 4; e++) {
                float ds = X[e * 132 + 128];
                acc[e][0] = fmaf(ds, wv.x, acc[e][0]);
                acc[e][1] = fmaf(ds, wv.y, acc[e][1]);
            }
        }
        __syncwarp();  // all lanes done reading x before we overwrite with m
        #pragma unroll
        for (int e = 0; e < 4; e++) {
            *(float2*)(X + e * 64 + j0) =
                make_float2(silu(acc[e][0]), silu(acc[e][1]));
        }
        __syncwarp();

        // ---- edge MLP layer 2: (64 -> 64), SiLU  -> edge_msg
        float acc2[4][2];
        {
            float b0 = be2s[j0], b1 = be2s[j0 + 1];
            #pragma unroll
            for (int e = 0; e < 4; e++) { acc2[e][0] = b0; acc2[e][1] = b1; }
        }
        #pragma unroll 2
        for (int k = 0; k < 64; k += 4) {
            float xv[4][4];
            #pragma unroll
            for (int e = 0; e < 4; e++) {
                float4 q = *(const float4*)(X + e * 64 + k);
                xv[e][0] = q.x; xv[e][1] = q.y; xv[e][2] = q.z; xv[e][3] = q.w;
            }
            #pragma unroll
            for (int kk = 0; kk < 4; kk++) {
                float2 wv = *(const float2*)(We2s + (k + kk) * 64 + j0);
                #pragma unroll
                for (int e = 0; e < 4; e++) {
                    acc2[e][0] = fmaf(xv[e][kk], wv.x, acc2[e][0]);
                    acc2[e][1] = fmaf(xv[e][kk], wv.y, acc2[e][1]);
                }
            }
        }
        float em[4][2];
        #pragma unroll
        for (int e = 0; e < 4; e++) {
            em[e][0] = silu(acc2[e][0]);
            em[e][1] = silu(acc2[e][1]);
            // store edge_msg to scratch region [256..512) (no overlap with m)
            *(float2*)(X + 256 + e * 64 + j0) = make_float2(em[e][0], em[e][1]);
        }
        __syncwarp();

        // ---- coord MLP layer 1: (64 -> 64), SiLU
        float acc3[4][2];
        {
            float b0 = bc1s[j0], b1 = bc1s[j0 + 1];
            #pragma unroll
            for (int e = 0; e < 4; e++) { acc3[e][0] = b0; acc3[e][1] = b1; }
        }
        #pragma unroll 2
        for (int k = 0; k < 64; k += 4) {
            float xv[4][4];
            #pragma unroll
            for (int e = 0; e < 4; e++) {
                float4 q = *(const float4*)(X + 256 + e * 64 + k);
                xv[e][0] = q.x; xv[e][1] = q.y; xv[e][2] = q.z; xv[e][3] = q.w;
            }
            #pragma unroll
            for (int kk = 0; kk < 4; kk++) {
                float2 wv = *(const float2*)(Wc1s + (k + kk) * 64 + j0);
                #pragma unroll
                for (int e = 0; e < 4; e++) {
                    acc3[e][0] = fmaf(xv[e][kk], wv.x, acc3[e][0]);
                    acc3[e][1] = fmaf(xv[e][kk], wv.y, acc3[e][1]);
                }
            }
        }
        // ---- coord MLP layer 2: (64 -> 1) via warp reduction
        float cw[4];
        {
            float w0 = Wc2s[j0], w1 = Wc2s[j0 + 1];
            #pragma unroll
            for (int e = 0; e < 4; e++) {
                float v = fmaf(silu(acc3[e][0]), w0, silu(acc3[e][1]) * w1);
                v += __shfl_xor_sync(0xffffffffu, v, 16);
                v += __shfl_xor_sync(0xffffffffu, v, 8);
                v += __shfl_xor_sync(0xffffffffu, v, 4);
                v += __shfl_xor_sync(0xffffffffu, v, 2);
                v += __shfl_xor_sync(0xffffffffu, v, 1);
                cw[e] = v + bc2v;
            }
        }

        // ---- scatter: message aggregation + coord aggregation
        #pragma unroll
        for (int e = 0; e < 4; e++) {
            float* dst = g_msg + (size_t)rw[e] * 64 + j0;
            atomicAdd(dst,     em[e][0]);
            atomicAdd(dst + 1, em[e][1]);
        }
        if (lane < 12) {
            const int e = lane / 3;
            const int c = lane - e * 3;
            atomicAdd(g_coord + (size_t)rw[e] * 3 + c, rl[lane] * cw[e]);
        }
    }
}

// ---------------------------------------------------------------------------
// Node kernel: warp processes 4 nodes at a time.
// node_input = [h | msg_agg] (128) -> 64 SiLU -> 64 linear; pos_out = pos+agg.
// ---------------------------------------------------------------------------
__global__ __launch_bounds__(256, 2) void node_kernel(
    const float* __restrict__ h, const float* __restrict__ pos,
    const float* __restrict__ Wn1, const float* __restrict__ bn1,
    const float* __restrict__ Wn2, const float* __restrict__ bn2,
    float* __restrict__ hout, float* __restrict__ posout)
{
    extern __shared__ float sm[];
    float* Wn1s = sm;                 // 128*64 = 8192
    float* Wn2s = Wn1s + 128 * 64;    // 4096
    float* bn1s = Wn2s + 64 * 64;     // 64
    float* bn2s = bn1s + 64;          // 64
    float* scr  = bn2s + 64;          // 8*512

    const int tid = threadIdx.x;
    for (int i = tid; i < 128 * 64; i += 256) Wn1s[i] = Wn1[i];
    for (int i = tid; i < 64 * 64; i += 256) Wn2s[i] = Wn2[i];
    if (tid < 64) { bn1s[tid] = bn1[tid]; bn2s[tid] = bn2[tid]; }
    __syncthreads();

    const int lane = tid & 31;
    const int w = tid >> 5;
    const int j0 = lane * 2;
    float* X = scr + w * 512;

    const int nTiles = N_NODES / 4;     // 12500
    const int warpStride = gridDim.x * 8;

    for (int t = blockIdx.x * 8 + w; t < nTiles; t += warpStride) {
        __syncwarp();
        const int base = t * 4;
        #pragma unroll
        for (int e = 0; e < 4; e++) {
            const int n = base + e;
            ((float2*)(X + e * 128))[lane]      = ((const float2*)(h + (size_t)n * 64))[lane];
            ((float2*)(X + e * 128 + 64))[lane] = ((const float2*)(g_msg + (size_t)n * 64))[lane];
        }
        __syncwarp();

        // node MLP layer 1: (128 -> 64), SiLU
        float acc[4][2];
        {
            float b0 = bn1s[j0], b1 = bn1s[j0 + 1];
            #pragma unroll
            for (int e = 0; e < 4; e++) { acc[e][0] = b0; acc[e][1] = b1; }
        }
        #pragma unroll 2
        for (int k = 0; k < 128; k += 4) {
            float xv[4][4];
            #pragma unroll
            for (int e = 0; e < 4; e++) {
                float4 q = *(const float4*)(X + e * 128 + k);
                xv[e][0] = q.x; xv[e][1] = q.y; xv[e][2] = q.z; xv[e][3] = q.w;
            }
            #pragma unroll
            for (int kk = 0; kk < 4; kk++) {
                float2 wv = *(const float2*)(Wn1s + (k + kk) * 64 + j0);
                #pragma unroll
                for (int e = 0; e < 4; e++) {
                    acc[e][0] = fmaf(xv[e][kk], wv.x, acc[e][0]);
                    acc[e][1] = fmaf(xv[e][kk], wv.y, acc[e][1]);
                }
            }
        }
        __syncwarp();
        #pragma unroll
        for (int e = 0; e < 4; e++) {
            *(float2*)(X + e * 64 + j0) =
                make_float2(silu(acc[e][0]), silu(acc[e][1]));
        }
        __syncwarp();

        // node MLP layer 2: (64 -> 64), linear
        float acc2[4][2];
        {
            float b0 = bn2s[j0], b1 = bn2s[j0 + 1];
            #pragma unroll
            for (int e = 0; e < 4; e++) { acc2[e][0] = b0; acc2[e][1] = b1; }
        }
        #pragma unroll 2
        for (int k = 0; k < 64; k += 4) {
            float xv[4][4];
            #pragma unroll
            for (int e = 0; e < 4; e++) {
                float4 q = *(const float4*)(X + e * 64 + k);
                xv[e][0] = q.x; xv[e][1] = q.y; xv[e][2] = q.z; xv[e][3] = q.w;
            }
            #pragma unroll
            for (int kk = 0; kk < 4; kk++) {
                float2 wv = *(const float2*)(Wn2s + (k + kk) * 64 + j0);
                #pragma unroll
                for (int e = 0; e < 4; e++) {
                    acc2[e][0] = fmaf(xv[e][kk], wv.x, acc2[e][0]);
                    acc2[e][1] = fmaf(xv[e][kk], wv.y, acc2[e][1]);
                }
            }
        }
        #pragma unroll
        for (int e = 0; e < 4; e++) {
            const int n = base + e;
            ((float2*)(hout + (size_t)n * 64))[lane] =
                make_float2(acc2[e][0], acc2[e][1]);
        }
        if (lane < 12) {
            const int e = lane / 3;
            const int c = lane - e * 3;
            const int n = base + e;
            posout[n * 3 + c] = pos[n * 3 + c] + g_coord[n * 3 + c];
        }
    }
}

// ---------------------------------------------------------------------------
extern "C" void kernel_launch(void* const* d_in, const int* in_sizes, int n_in,
                              void* d_out, int out_size)
{
    const float* h   = (const float*)d_in[0];
    const float* pos = (const float*)d_in[1];
    const unsigned int* ei_words = (const unsigned int*)d_in[2];
    const float* We1 = (const float*)d_in[3];
    const float* be1 = (const float*)d_in[4];
    const float* We2 = (const float*)d_in[5];
    const float* be2 = (const float*)d_in[6];
    const float* Wc1 = (const float*)d_in[7];
    const float* bc1 = (const float*)d_in[8];
    const float* Wc2 = (const float*)d_in[9];
    const float* bc2 = (const float*)d_in[10];
    const float* Wn1 = (const float*)d_in[11];
    const float* bn1 = (const float*)d_in[12];
    const float* Wn2 = (const float*)d_in[13];
    const float* bn2 = (const float*)d_in[14];

    float* hout   = (float*)d_out;
    float* posout = hout + (size_t)N_NODES * 64;

    void* msgPtr = nullptr;
    void* coordPtr = nullptr;
    cudaGetSymbolAddress(&msgPtr, g_msg);
    cudaGetSymbolAddress(&coordPtr, g_coord);
    cudaMemsetAsync(msgPtr, 0, sizeof(float) * (size_t)N_NODES * 64);
    cudaMemsetAsync(coordPtr, 0, sizeof(float) * (size_t)N_NODES * 3);

    decode_edges<<<1024, 256>>>(ei_words);

    const int EDGE_SMEM = (129 * 64 + 2 * 64 * 64 + 4 * 64 + 8 * 528 + 96 + 64) * 4;
    const int NODE_SMEM = (128 * 64 + 64 * 64 + 2 * 64 + 8 * 512) * 4;

    cudaFuncSetAttribute(edge_kernel, cudaFuncAttributeMaxDynamicSharedMemorySize, EDGE_SMEM);
    cudaFuncSetAttribute(node_kernel, cudaFuncAttributeMaxDynamicSharedMemorySize, NODE_SMEM);

    edge_kernel<<<304, 256, EDGE_SMEM>>>(h, pos,
                                         We1, be1, We2, be2,
                                         Wc1, bc1, Wc2, bc2);
    node_kernel<<<304, 256, NODE_SMEM>>>(h, pos, Wn1, bn1, Wn2, bn2,
                                         hout, posout);
}

// round 7
// speedup vs baseline: 1.3486x; 1.3486x over previous
#include <cuda_runtime.h>

#define N_NODES 50000
#define N_EDGES 800000

#define EB 8                      // edges per warp-tile
#define NTILES (N_EDGES / EB)     // 100000
#define EWARPS 16                 // warps per edge-kernel CTA
#define WSCR 2368                 // per-warp scratch floats (16B-aligned chunk)

// Scatter-aggregation scratch + decoded edge indices
__device__ float g_msg[N_NODES * 64];
__device__ float g_coord[N_NODES * 3];
__device__ int   g_row[N_EDGES];
__device__ int   g_col[N_EDGES];

__device__ __forceinline__ float silu(float x) {
    return x * (1.0f / (1.0f + __expf(-x)));
}

// ---- packed fp32x2 helpers (sm_100+ PTX) -----------------------------------
__device__ __forceinline__ unsigned long long pack2(float lo, float hi) {
    unsigned long long r;
    asm("mov.b64 %0, {%1, %2};" : "=l"(r) : "f"(lo), "f"(hi));
    return r;
}
__device__ __forceinline__ unsigned long long dup2(float v) {
    unsigned long long r;
    asm("mov.b64 %0, {%1, %1};" : "=l"(r) : "f"(v));
    return r;
}
__device__ __forceinline__ void unpack2(unsigned long long p, float& lo, float& hi) {
    asm("mov.b64 {%0, %1}, %2;" : "=f"(lo), "=f"(hi) : "l"(p));
}
__device__ __forceinline__ void ffma2(unsigned long long& d,
                                      unsigned long long a,
                                      unsigned long long b) {
    asm("fma.rn.f32x2 %0, %1, %2, %0;" : "+l"(d) : "l"(a), "l"(b));
}

// ---------------------------------------------------------------------------
// Decode edge_index (reference claims int64; JAX x64-off emits int32 — detect).
// ---------------------------------------------------------------------------
__global__ void decode_edges(const unsigned int* __restrict__ w) {
    __shared__ int is64_s;
    if (threadIdx.x == 0) {
        int is64 = 1;
        #pragma unroll 1
        for (int i = 1; i < 128; i += 2)
            if (w[i] != 0u) { is64 = 0; break; }
        is64_s = is64;
    }
    __syncthreads();
    const int is64 = is64_s;
    const int total = 2 * N_EDGES;
    for (int i = blockIdx.x * blockDim.x + threadIdx.x; i < total;
         i += gridDim.x * blockDim.x) {
        int v = is64 ? (int)w[2 * i] : (int)w[i];
        v = max(0, min(v, N_NODES - 1));
        if (i < N_EDGES) g_row[i] = v;
        else             g_col[i - N_EDGES] = v;
    }
}

// ---------------------------------------------------------------------------
// Edge kernel v2: warp processes 8 edges; math in packed f32x2 (FFMA2).
// Lane owns output cols j0=2*lane, j0+1; accumulators are edge-pairs.
// Scratch layout: activations edge-interleaved, row stride 12 floats
// (16B-aligned v2.u64 x-pair loads for every row k).
// ---------------------------------------------------------------------------
__global__ __launch_bounds__(512, 1) void edge_kernel(
    const float* __restrict__ h, const float* __restrict__ pos,
    const float* __restrict__ We1, const float* __restrict__ be1,
    const float* __restrict__ We2, const float* __restrict__ be2,
    const float* __restrict__ Wc1, const float* __restrict__ bc1,
    const float* __restrict__ Wc2, const float* __restrict__ bc2)
{
    extern __shared__ float sm[];
    float* We1s = sm;                       // 129*64 = 8256
    float* We2s = We1s + 129 * 64;          // 4096
    float* Wc1s = We2s + 64 * 64;           // 4096
    float* be1s = Wc1s + 64 * 64;           // 64
    float* be2s = be1s + 64;                // 64
    float* bc1s = be2s + 64;                // 64
    float* Wc2s = bc1s + 64;                // 64
    float* scr  = Wc2s + 64;                // 16 * WSCR

    const int tid = threadIdx.x;
    for (int i = tid; i < 129 * 64; i += 512) We1s[i] = We1[i];
    for (int i = tid; i < 64 * 64; i += 512) { We2s[i] = We2[i]; Wc1s[i] = Wc1[i]; }
    if (tid < 64) {
        be1s[tid] = be1[tid]; be2s[tid] = be2[tid];
        bc1s[tid] = bc1[tid]; Wc2s[tid] = Wc2[tid];
    }
    __syncthreads();

    const float bc2v = __ldg(bc2);
    const int lane = tid & 31;
    const int w    = tid >> 5;
    const int j0   = lane * 2;

    float* X1  = scr + w * WSCR;            // 129 rows * 12 = 1548 (layer1 in / em)
    float* X2  = X1 + 1548;                 // 64 rows * 12 = 768  (m)
    float* rl  = X2 + 768;                  // 24  rel_pos
    float* cwS = rl + 24;                   // 8   coord weights
    int*   idx = (int*)(cwS + 8);           // 16  (rw 8 | cl 8)

    const int warpStride = gridDim.x * EWARPS;

    for (int t = blockIdx.x * EWARPS + w; t < NTILES; t += warpStride) {
        __syncwarp();
        const int base = t * EB;
        if (lane < EB) {
            idx[lane]      = g_row[base + lane];
            idx[EB + lane] = g_col[base + lane];
        }
        __syncwarp();

        // ---- stage x = [h_row | h_col | ds] edge-interleaved (stride 12)
        #pragma unroll
        for (int e = 0; e < EB; e++) {
            const int r = idx[e], c = idx[EB + e];
            float a0 = h[(size_t)r * 64 + lane];
            float a1 = h[(size_t)r * 64 + 32 + lane];
            float b0 = h[(size_t)c * 64 + lane];
            float b1 = h[(size_t)c * 64 + 32 + lane];
            X1[(lane)      * 12 + e] = a0;
            X1[(lane + 32) * 12 + e] = a1;
            X1[(lane + 64) * 12 + e] = b0;
            X1[(lane + 96) * 12 + e] = b1;
        }
        if (lane < EB) {
            const int e = lane;
            const int r = idx[e], c = idx[EB + e];
            float dx = pos[r * 3 + 0] - pos[c * 3 + 0];
            float dy = pos[r * 3 + 1] - pos[c * 3 + 1];
            float dz = pos[r * 3 + 2] - pos[c * 3 + 2];
            rl[e * 3 + 0] = dx; rl[e * 3 + 1] = dy; rl[e * 3 + 2] = dz;
            X1[128 * 12 + e] = dx * dx + dy * dy + dz * dz;
        }
        __syncwarp();

        // ---- layer 1: (129 -> 64), SiLU   [acc = edge-pairs x 2 cols]
        unsigned long long a1c0[4], a1c1[4];
        {
            unsigned long long b0 = dup2(be1s[j0]), b1 = dup2(be1s[j0 + 1]);
            #pragma unroll
            for (int p = 0; p < 4; p++) { a1c0[p] = b0; a1c1[p] = b1; }
        }
        #pragma unroll 4
        for (int k = 0; k < 129; k++) {
            ulonglong2 xa = *(const ulonglong2*)(X1 + k * 12);
            ulonglong2 xb = *(const ulonglong2*)(X1 + k * 12 + 4);
            float2 wv = *(const float2*)(We1s + k * 64 + j0);
            unsigned long long w0 = dup2(wv.x), w1 = dup2(wv.y);
            ffma2(a1c0[0], xa.x, w0); ffma2(a1c1[0], xa.x, w1);
            ffma2(a1c0[1], xa.y, w0); ffma2(a1c1[1], xa.y, w1);
            ffma2(a1c0[2], xb.x, w0); ffma2(a1c1[2], xb.x, w1);
            ffma2(a1c0[3], xb.y, w0); ffma2(a1c1[3], xb.y, w1);
        }
        #pragma unroll
        for (int p = 0; p < 4; p++) {
            float lo, hi;
            unpack2(a1c0[p], lo, hi);
            *(unsigned long long*)(X2 + (j0) * 12 + 2 * p) = pack2(silu(lo), silu(hi));
            unpack2(a1c1[p], lo, hi);
            *(unsigned long long*)(X2 + (j0 + 1) * 12 + 2 * p) = pack2(silu(lo), silu(hi));
        }
        __syncwarp();

        // ---- layer 2: (64 -> 64), SiLU -> edge_msg (stored into X1 rows 0..63)
        unsigned long long a2c0[4], a2c1[4];
        {
            unsigned long long b0 = dup2(be2s[j0]), b1 = dup2(be2s[j0 + 1]);
            #pragma unroll
            for (int p = 0; p < 4; p++) { a2c0[p] = b0; a2c1[p] = b1; }
        }
        #pragma unroll 4
        for (int k = 0; k < 64; k++) {
            ulonglong2 xa = *(const ulonglong2*)(X2 + k * 12);
            ulonglong2 xb = *(const ulonglong2*)(X2 + k * 12 + 4);
            float2 wv = *(const float2*)(We2s + k * 64 + j0);
            unsigned long long w0 = dup2(wv.x), w1 = dup2(wv.y);
            ffma2(a2c0[0], xa.x, w0); ffma2(a2c1[0], xa.x, w1);
            ffma2(a2c0[1], xa.y, w0); ffma2(a2c1[1], xa.y, w1);
            ffma2(a2c0[2], xb.x, w0); ffma2(a2c1[2], xb.x, w1);
            ffma2(a2c0[3], xb.y, w0); ffma2(a2c1[3], xb.y, w1);
        }
        float eml0[4], emh0[4], eml1[4], emh1[4];
        #pragma unroll
        for (int p = 0; p < 4; p++) {
            float lo, hi;
            unpack2(a2c0[p], lo, hi);
            eml0[p] = silu(lo); emh0[p] = silu(hi);
            *(unsigned long long*)(X1 + (j0) * 12 + 2 * p) = pack2(eml0[p], emh0[p]);
            unpack2(a2c1[p], lo, hi);
            eml1[p] = silu(lo); emh1[p] = silu(hi);
            *(unsigned long long*)(X1 + (j0 + 1) * 12 + 2 * p) = pack2(eml1[p], emh1[p]);
        }
        __syncwarp();

        // ---- coord MLP layer 1: (64 -> 64), SiLU (acc in regs)
        unsigned long long a3c0[4], a3c1[4];
        {
            unsigned long long b0 = dup2(bc1s[j0]), b1 = dup2(bc1s[j0 + 1]);
            #pragma unroll
            for (int p = 0; p < 4; p++) { a3c0[p] = b0; a3c1[p] = b1; }
        }
        #pragma unroll 4
        for (int k = 0; k < 64; k++) {
            ulonglong2 xa = *(const ulonglong2*)(X1 + k * 12);
            ulonglong2 xb = *(const ulonglong2*)(X1 + k * 12 + 4);
            float2 wv = *(const float2*)(Wc1s + k * 64 + j0);
            unsigned long long w0 = dup2(wv.x), w1 = dup2(wv.y);
            ffma2(a3c0[0], xa.x, w0); ffma2(a3c1[0], xa.x, w1);
            ffma2(a3c0[1], xa.y, w0); ffma2(a3c1[1], xa.y, w1);
            ffma2(a3c0[2], xb.x, w0); ffma2(a3c1[2], xb.x, w1);
            ffma2(a3c0[3], xb.y, w0); ffma2(a3c1[3], xb.y, w1);
        }
        // ---- coord MLP layer 2: (64 -> 1), warp reduction per edge
        {
            const float w0 = Wc2s[j0], w1 = Wc2s[j0 + 1];
            float cwe[8];
            #pragma unroll
            for (int p = 0; p < 4; p++) {
                float lo0, hi0, lo1, hi1;
                unpack2(a3c0[p], lo0, hi0);
                unpack2(a3c1[p], lo1, hi1);
                cwe[2 * p]     = fmaf(silu(lo0), w0, silu(lo1) * w1);
                cwe[2 * p + 1] = fmaf(silu(hi0), w0, silu(hi1) * w1);
            }
            #pragma unroll
            for (int e = 0; e < 8; e++) {
                float v = cwe[e];
                v += __shfl_xor_sync(0xffffffffu, v, 16);
                v += __shfl_xor_sync(0xffffffffu, v, 8);
                v += __shfl_xor_sync(0xffffffffu, v, 4);
                v += __shfl_xor_sync(0xffffffffu, v, 2);
                v += __shfl_xor_sync(0xffffffffu, v, 1);
                if (lane == 0) cwS[e] = v + bc2v;
            }
        }
        __syncwarp();

        // ---- scatter: message aggregation
        #pragma unroll
        for (int p = 0; p < 4; p++) {
            const int r0 = idx[2 * p], r1 = idx[2 * p + 1];
            atomicAdd(g_msg + (size_t)r0 * 64 + j0,     eml0[p]);
            atomicAdd(g_msg + (size_t)r0 * 64 + j0 + 1, eml1[p]);
            atomicAdd(g_msg + (size_t)r1 * 64 + j0,     emh0[p]);
            atomicAdd(g_msg + (size_t)r1 * 64 + j0 + 1, emh1[p]);
        }
        // ---- scatter: coord aggregation (24 lanes: 8 edges x 3 comps)
        if (lane < 24) {
            const int e = lane / 3;
            const int c = lane - e * 3;
            atomicAdd(g_coord + (size_t)idx[e] * 3 + c, rl[lane] * cwS[e]);
        }
    }
}

// ---------------------------------------------------------------------------
// Node kernel (unchanged from passing version): warp per 4 nodes.
// ---------------------------------------------------------------------------
__global__ __launch_bounds__(256, 2) void node_kernel(
    const float* __restrict__ h, const float* __restrict__ pos,
    const float* __restrict__ Wn1, const float* __restrict__ bn1,
    const float* __restrict__ Wn2, const float* __restrict__ bn2,
    float* __restrict__ hout, float* __restrict__ posout)
{
    extern __shared__ float sm[];
    float* Wn1s = sm;
    float* Wn2s = Wn1s + 128 * 64;
    float* bn1s = Wn2s + 64 * 64;
    float* bn2s = bn1s + 64;
    float* scr  = bn2s + 64;

    const int tid = threadIdx.x;
    for (int i = tid; i < 128 * 64; i += 256) Wn1s[i] = Wn1[i];
    for (int i = tid; i < 64 * 64; i += 256) Wn2s[i] = Wn2[i];
    if (tid < 64) { bn1s[tid] = bn1[tid]; bn2s[tid] = bn2[tid]; }
    __syncthreads();

    const int lane = tid & 31;
    const int w = tid >> 5;
    const int j0 = lane * 2;
    float* X = scr + w * 512;

    const int nTiles = N_NODES / 4;
    const int warpStride = gridDim.x * 8;

    for (int t = blockIdx.x * 8 + w; t < nTiles; t += warpStride) {
        __syncwarp();
        const int base = t * 4;
        #pragma unroll
        for (int e = 0; e < 4; e++) {
            const int n = base + e;
            ((float2*)(X + e * 128))[lane]      = ((const float2*)(h + (size_t)n * 64))[lane];
            ((float2*)(X + e * 128 + 64))[lane] = ((const float2*)(g_msg + (size_t)n * 64))[lane];
        }
        __syncwarp();

        float acc[4][2];
        {
            float b0 = bn1s[j0], b1 = bn1s[j0 + 1];
            #pragma unroll
            for (int e = 0; e < 4; e++) { acc[e][0] = b0; acc[e][1] = b1; }
        }
        #pragma unroll 2
        for (int k = 0; k < 128; k += 4) {
            float xv[4][4];
            #pragma unroll
            for (int e = 0; e < 4; e++) {
                float4 q = *(const float4*)(X + e * 128 + k);
                xv[e][0] = q.x; xv[e][1] = q.y; xv[e][2] = q.z; xv[e][3] = q.w;
            }
            #pragma unroll
            for (int kk = 0; kk < 4; kk++) {
                float2 wv = *(const float2*)(Wn1s + (k + kk) * 64 + j0);
                #pragma unroll
                for (int e = 0; e < 4; e++) {
                    acc[e][0] = fmaf(xv[e][kk], wv.x, acc[e][0]);
                    acc[e][1] = fmaf(xv[e][kk], wv.y, acc[e][1]);
                }
            }
        }
        __syncwarp();
        #pragma unroll
        for (int e = 0; e < 4; e++) {
            *(float2*)(X + e * 64 + j0) =
                make_float2(silu(acc[e][0]), silu(acc[e][1]));
        }
        __syncwarp();

        float acc2[4][2];
        {
            float b0 = bn2s[j0], b1 = bn2s[j0 + 1];
            #pragma unroll
            for (int e = 0; e < 4; e++) { acc2[e][0] = b0; acc2[e][1] = b1; }
        }
        #pragma unroll 2
        for (int k = 0; k < 64; k += 4) {
            float xv[4][4];
            #pragma unroll
            for (int e = 0; e < 4; e++) {
                float4 q = *(const float4*)(X + e * 64 + k);
                xv[e][0] = q.x; xv[e][1] = q.y; xv[e][2] = q.z; xv[e][3] = q.w;
            }
            #pragma unroll
            for (int kk = 0; kk < 4; kk++) {
                float2 wv = *(const float2*)(Wn2s + (k + kk) * 64 + j0);
                #pragma unroll
                for (int e = 0; e < 4; e++) {
                    acc2[e][0] = fmaf(xv[e][kk], wv.x, acc2[e][0]);
                    acc2[e][1] = fmaf(xv[e][kk], wv.y, acc2[e][1]);
                }
            }
        }
        #pragma unroll
        for (int e = 0; e < 4; e++) {
            const int n = base + e;
            ((float2*)(hout + (size_t)n * 64))[lane] =
                make_float2(acc2[e][0], acc2[e][1]);
        }
        if (lane < 12) {
            const int e = lane / 3;
            const int c = lane - e * 3;
            const int n = base + e;
            posout[n * 3 + c] = pos[n * 3 + c] + g_coord[n * 3 + c];
        }
    }
}

// ---------------------------------------------------------------------------
extern "C" void kernel_launch(void* const* d_in, const int* in_sizes, int n_in,
                              void* d_out, int out_size)
{
    const float* h   = (const float*)d_in[0];
    const float* pos = (const float*)d_in[1];
    const unsigned int* ei_words = (const unsigned int*)d_in[2];
    const float* We1 = (const float*)d_in[3];
    const float* be1 = (const float*)d_in[4];
    const float* We2 = (const float*)d_in[5];
    const float* be2 = (const float*)d_in[6];
    const float* Wc1 = (const float*)d_in[7];
    const float* bc1 = (const float*)d_in[8];
    const float* Wc2 = (const float*)d_in[9];
    const float* bc2 = (const float*)d_in[10];
    const float* Wn1 = (const float*)d_in[11];
    const float* bn1 = (const float*)d_in[12];
    const float* Wn2 = (const float*)d_in[13];
    const float* bn2 = (const float*)d_in[14];

    float* hout   = (float*)d_out;
    float* posout = hout + (size_t)N_NODES * 64;

    void* msgPtr = nullptr;
    void* coordPtr = nullptr;
    cudaGetSymbolAddress(&msgPtr, g_msg);
    cudaGetSymbolAddress(&coordPtr, g_coord);
    cudaMemsetAsync(msgPtr, 0, sizeof(float) * (size_t)N_NODES * 64);
    cudaMemsetAsync(coordPtr, 0, sizeof(float) * (size_t)N_NODES * 3);

    decode_edges<<<1024, 256>>>(ei_words);

    const int EDGE_SMEM = (129 * 64 + 2 * 64 * 64 + 4 * 64 + EWARPS * WSCR) * 4;
    const int NODE_SMEM = (128 * 64 + 64 * 64 + 2 * 64 + 8 * 512) * 4;

    cudaFuncSetAttribute(edge_kernel, cudaFuncAttributeMaxDynamicSharedMemorySize, EDGE_SMEM);
    cudaFuncSetAttribute(node_kernel, cudaFuncAttributeMaxDynamicSharedMemorySize, NODE_SMEM);

    edge_kernel<<<152, 512, EDGE_SMEM>>>(h, pos,
                                         We1, be1, We2, be2,
                                         Wc1, bc1, Wc2, bc2);
    node_kernel<<<304, 256, NODE_SMEM>>>(h, pos, Wn1, bn1, Wn2, bn2,
                                         hout, posout);
}

// round 8
// speedup vs baseline: 1.4025x; 1.0400x over previous
#include <cuda_runtime.h>

#define N_NODES 50000
#define N_EDGES 800000

#define EB 8                      // edges per warp-tile
#define NTILES (N_EDGES / EB)     // 100000
#define EWARPS 20                 // warps per edge-kernel CTA
#define XSTR 20                   // padded row stride (floats) in Xm
#define WSCR 1360                 // per-warp scratch floats

// Device-global scratch (allocation rules forbid cudaMalloc)
__device__ float g_msg[N_NODES * 64];
__device__ float g_coord[N_NODES * 3];
__device__ float g_pa[N_NODES * 64];      // h @ We1[0:64]
__device__ float g_pb[N_NODES * 64];      // h @ We1[64:128]
__device__ int   g_row[N_EDGES];
__device__ int   g_col[N_EDGES];

__device__ __forceinline__ float silu(float x) {
    return x * (1.0f / (1.0f + __expf(-x)));
}

// ---- packed fp32x2 helpers --------------------------------------------------
__device__ __forceinline__ unsigned long long pack2(float lo, float hi) {
    unsigned long long r;
    asm("mov.b64 %0, {%1, %2};" : "=l"(r) : "f"(lo), "f"(hi));
    return r;
}
__device__ __forceinline__ void unpack2(unsigned long long p, float& lo, float& hi) {
    asm("mov.b64 {%0, %1}, %2;" : "=f"(lo), "=f"(hi) : "l"(p));
}
__device__ __forceinline__ void ffma2(unsigned long long& d,
                                      unsigned long long a,
                                      unsigned long long b) {
    asm("fma.rn.f32x2 %0, %1, %2, %0;" : "+l"(d) : "l"(a), "l"(b));
}
__device__ __forceinline__ unsigned long long add2(unsigned long long a,
                                                   unsigned long long b) {
    unsigned long long r;
    asm("add.rn.f32x2 %0, %1, %2;" : "=l"(r) : "l"(a), "l"(b));
    return r;
}

// ---------------------------------------------------------------------------
// Decode edge_index (reference claims int64; JAX x64-off emits int32 — detect).
// ---------------------------------------------------------------------------
__global__ void decode_edges(const unsigned int* __restrict__ w) {
    __shared__ int is64_s;
    if (threadIdx.x == 0) {
        int is64 = 1;
        #pragma unroll 1
        for (int i = 1; i < 128; i += 2)
            if (w[i] != 0u) { is64 = 0; break; }
        is64_s = is64;
    }
    __syncthreads();
    const int is64 = is64_s;
    const int total = 2 * N_EDGES;
    for (int i = blockIdx.x * blockDim.x + threadIdx.x; i < total;
         i += gridDim.x * blockDim.x) {
        int v = is64 ? (int)w[2 * i] : (int)w[i];
        v = max(0, min(v, N_NODES - 1));
        if (i < N_EDGES) g_row[i] = v;
        else             g_col[i - N_EDGES] = v;
    }
}

// ---------------------------------------------------------------------------
// Projection kernel: P_a = h @ We1[0:64], P_b = h @ We1[64:128].
// Warp per 4 nodes, lane owns cols j0 = 2*lane, j0+1.
// ---------------------------------------------------------------------------
__global__ __launch_bounds__(256, 2) void proj_kernel(
    const float* __restrict__ h, const float* __restrict__ We1)
{
    extern __shared__ float sm[];
    float* Ws  = sm;                 // 128*64 = 8192 (rows 0..127 of We1)
    float* scr = Ws + 128 * 64;      // 8 warps * 256

    const int tid = threadIdx.x;
    for (int i = tid; i < 128 * 64; i += 256) Ws[i] = We1[i];
    __syncthreads();

    const int lane = tid & 31;
    const int w = tid >> 5;
    const int j0 = lane * 2;
    float* X = scr + w * 256;

    const int nTiles = N_NODES / 4;     // 12500
    const int warpStride = gridDim.x * 8;

    for (int t = blockIdx.x * 8 + w; t < nTiles; t += warpStride) {
        __syncwarp();
        const int base = t * 4;
        #pragma unroll
        for (int e = 0; e < 4; e++)
            ((float2*)(X + e * 64))[lane] = ((const float2*)(h + (size_t)(base + e) * 64))[lane];
        __syncwarp();

        float pa[4][2], pb[4][2];
        #pragma unroll
        for (int e = 0; e < 4; e++) {
            pa[e][0] = 0.f; pa[e][1] = 0.f; pb[e][0] = 0.f; pb[e][1] = 0.f;
        }
        #pragma unroll 2
        for (int k = 0; k < 64; k += 4) {
            float xv[4][4];
            #pragma unroll
            for (int e = 0; e < 4; e++) {
                float4 q = *(const float4*)(X + e * 64 + k);
                xv[e][0] = q.x; xv[e][1] = q.y; xv[e][2] = q.z; xv[e][3] = q.w;
            }
            #pragma unroll
            for (int kk = 0; kk < 4; kk++) {
                float2 wa = *(const float2*)(Ws + (k + kk) * 64 + j0);
                float2 wb = *(const float2*)(Ws + (64 + k + kk) * 64 + j0);
                #pragma unroll
                for (int e = 0; e < 4; e++) {
                    pa[e][0] = fmaf(xv[e][kk], wa.x, pa[e][0]);
                    pa[e][1] = fmaf(xv[e][kk], wa.y, pa[e][1]);
                    pb[e][0] = fmaf(xv[e][kk], wb.x, pb[e][0]);
                    pb[e][1] = fmaf(xv[e][kk], wb.y, pb[e][1]);
                }
            }
        }
        #pragma unroll
        for (int e = 0; e < 4; e++) {
            const int n = base + e;
            ((float2*)(g_pa + (size_t)n * 64))[lane] = make_float2(pa[e][0], pa[e][1]);
            ((float2*)(g_pb + (size_t)n * 64))[lane] = make_float2(pb[e][0], pb[e][1]);
        }
    }
}

// ---------------------------------------------------------------------------
// Edge kernel v3: layer1 replaced by gathered projections; layers 2/3 in
// packed FFMA2 with natural u64 weight loads (x pre-duplicated in shared).
// Warp per 8 edges; lane owns cols j0, j0+1; acc[e] = (col j0, col j0+1).
// ---------------------------------------------------------------------------
__global__ __launch_bounds__(EWARPS * 32, 1) void edge_kernel(
    const float* __restrict__ pos,
    const float* __restrict__ We1, const float* __restrict__ be1,
    const float* __restrict__ We2, const float* __restrict__ be2,
    const float* __restrict__ Wc1, const float* __restrict__ bc1,
    const float* __restrict__ Wc2, const float* __restrict__ bc2)
{
    extern __shared__ float sm[];
    float* We2s = sm;                  // 4096
    float* Wc1s = We2s + 64 * 64;      // 4096
    float* wdss = Wc1s + 64 * 64;      // 64  (We1 row 128: dist_sq weights)
    float* be1s = wdss + 64;           // 64
    float* be2s = be1s + 64;           // 64
    float* bc1s = be2s + 64;           // 64
    float* Wc2s = bc1s + 64;           // 64
    float* scr  = Wc2s + 64;           // EWARPS * WSCR

    const int tid = threadIdx.x;
    const int nthr = EWARPS * 32;
    for (int i = tid; i < 64 * 64; i += nthr) { We2s[i] = We2[i]; Wc1s[i] = Wc1[i]; }
    if (tid < 64) {
        wdss[tid] = We1[128 * 64 + tid];
        be1s[tid] = be1[tid]; be2s[tid] = be2[tid];
        bc1s[tid] = bc1[tid]; Wc2s[tid] = Wc2[tid];
    }
    __syncthreads();

    const float bc2v = __ldg(bc2);
    const int lane = tid & 31;
    const int w    = tid >> 5;
    const int j0   = lane * 2;

    float* Xm  = scr + w * WSCR;        // 64 rows * XSTR = 1280
    float* rl  = Xm + 64 * XSTR;        // 24
    float* cwS = rl + 24;               // 8
    unsigned long long* ds2 = (unsigned long long*)(cwS + 8);  // 8 u64
    int* idx = (int*)(ds2 + 8);         // 16

    const unsigned long long be1p = *(const unsigned long long*)(be1s + j0);
    const unsigned long long be2p = *(const unsigned long long*)(be2s + j0);
    const unsigned long long bc1p = *(const unsigned long long*)(bc1s + j0);
    const unsigned long long wdsp = *(const unsigned long long*)(wdss + j0);
    const float wc2_0 = Wc2s[j0], wc2_1 = Wc2s[j0 + 1];

    const int warpStride = gridDim.x * EWARPS;

    for (int t = blockIdx.x * EWARPS + w; t < NTILES; t += warpStride) {
        __syncwarp();
        const int base = t * EB;
        if (lane < EB) {
            idx[lane]      = g_row[base + lane];
            idx[EB + lane] = g_col[base + lane];
        }
        __syncwarp();

        // ---- gather projections (L2-resident), rel_pos/ds by lanes 0..7
        float2 pa[EB], pb[EB];
        #pragma unroll
        for (int e = 0; e < EB; e++) {
            pa[e] = *(const float2*)(g_pa + (size_t)idx[e] * 64 + j0);
            pb[e] = *(const float2*)(g_pb + (size_t)idx[EB + e] * 64 + j0);
        }
        if (lane < EB) {
            const int e = lane;
            const int r = idx[e], c = idx[EB + e];
            float dx = pos[r * 3 + 0] - pos[c * 3 + 0];
            float dy = pos[r * 3 + 1] - pos[c * 3 + 1];
            float dz = pos[r * 3 + 2] - pos[c * 3 + 2];
            rl[e * 3 + 0] = dx; rl[e * 3 + 1] = dy; rl[e * 3 + 2] = dz;
            float ds = dx * dx + dy * dy + dz * dz;
            ds2[e] = pack2(ds, ds);
        }
        __syncwarp();

        // ---- layer 1 (factored): silu(pa + pb + ds*wds + b) -> m, dup'd to Xm
        #pragma unroll
        for (int p = 0; p < 4; p++) {
            float v0l, v0h, v1l, v1h;
            {
                unsigned long long a = add2(pack2(pa[2 * p].x + pb[2 * p].x,
                                                  pa[2 * p].y + pb[2 * p].y), be1p);
                ffma2(a, ds2[2 * p], wdsp);
                float lo, hi; unpack2(a, lo, hi);
                v0l = silu(lo); v0h = silu(hi);
            }
            {
                unsigned long long a = add2(pack2(pa[2 * p + 1].x + pb[2 * p + 1].x,
                                                  pa[2 * p + 1].y + pb[2 * p + 1].y), be1p);
                ffma2(a, ds2[2 * p + 1], wdsp);
                float lo, hi; unpack2(a, lo, hi);
                v1l = silu(lo); v1h = silu(hi);
            }
            *(float4*)(Xm + j0 * XSTR + 4 * p)       = make_float4(v0l, v0l, v1l, v1l);
            *(float4*)(Xm + (j0 + 1) * XSTR + 4 * p) = make_float4(v0h, v0h, v1h, v1h);
        }
        __syncwarp();

        // ---- layer 2: (64 -> 64), SiLU -> edge_msg
        unsigned long long acc[EB];
        #pragma unroll
        for (int e = 0; e < EB; e++) acc[e] = be2p;
        #pragma unroll 4
        for (int k = 0; k < 64; k++) {
            const float* row = Xm + k * XSTR;
            ulonglong2 q01 = *(const ulonglong2*)(row);
            ulonglong2 q23 = *(const ulonglong2*)(row + 4);
            ulonglong2 q45 = *(const ulonglong2*)(row + 8);
            ulonglong2 q67 = *(const ulonglong2*)(row + 12);
            unsigned long long wp = *(const unsigned long long*)(We2s + k * 64 + j0);
            ffma2(acc[0], q01.x, wp); ffma2(acc[1], q01.y, wp);
            ffma2(acc[2], q23.x, wp); ffma2(acc[3], q23.y, wp);
            ffma2(acc[4], q45.x, wp); ffma2(acc[5], q45.y, wp);
            ffma2(acc[6], q67.x, wp); ffma2(acc[7], q67.y, wp);
        }
        __syncwarp();   // everyone done reading m before overwrite with em
        #pragma unroll
        for (int p = 0; p < 4; p++) {
            float l0, h0, l1, h1;
            unpack2(acc[2 * p], l0, h0);
            unpack2(acc[2 * p + 1], l1, h1);
            l0 = silu(l0); h0 = silu(h0); l1 = silu(l1); h1 = silu(h1);
            *(float4*)(Xm + j0 * XSTR + 4 * p)       = make_float4(l0, l0, l1, l1);
            *(float4*)(Xm + (j0 + 1) * XSTR + 4 * p) = make_float4(h0, h0, h1, h1);
        }
        __syncwarp();

        // ---- coord MLP layer 1: (64 -> 64), SiLU
        unsigned long long acc3[EB];
        #pragma unroll
        for (int e = 0; e < EB; e++) acc3[e] = bc1p;
        #pragma unroll 4
        for (int k = 0; k < 64; k++) {
            const float* row = Xm + k * XSTR;
            ulonglong2 q01 = *(const ulonglong2*)(row);
            ulonglong2 q23 = *(const ulonglong2*)(row + 4);
            ulonglong2 q45 = *(const ulonglong2*)(row + 8);
            ulonglong2 q67 = *(const ulonglong2*)(row + 12);
            unsigned long long wp = *(const unsigned long long*)(Wc1s + k * 64 + j0);
            ffma2(acc3[0], q01.x, wp); ffma2(acc3[1], q01.y, wp);
            ffma2(acc3[2], q23.x, wp); ffma2(acc3[3], q23.y, wp);
            ffma2(acc3[4], q45.x, wp); ffma2(acc3[5], q45.y, wp);
            ffma2(acc3[6], q67.x, wp); ffma2(acc3[7], q67.y, wp);
        }
        // ---- coord MLP layer 2: (64 -> 1), warp reduction per edge
        #pragma unroll
        for (int e = 0; e < EB; e++) {
            float lo, hi; unpack2(acc3[e], lo, hi);
            float v = fmaf(silu(lo), wc2_0, silu(hi) * wc2_1);
            v += __shfl_xor_sync(0xffffffffu, v, 16);
            v += __shfl_xor_sync(0xffffffffu, v, 8);
            v += __shfl_xor_sync(0xffffffffu, v, 4);
            v += __shfl_xor_sync(0xffffffffu, v, 2);
            v += __shfl_xor_sync(0xffffffffu, v, 1);
            if (lane == 0) cwS[e] = v + bc2v;
        }
        __syncwarp();

        // ---- scatter: messages (em read back from Xm) + coords
        #pragma unroll
        for (int e = 0; e < EB; e++) {
            const int r = idx[e];
            float l = Xm[j0 * XSTR + 2 * e];
            float h2 = Xm[(j0 + 1) * XSTR + 2 * e];
            atomicAdd(g_msg + (size_t)r * 64 + j0,     l);
            atomicAdd(g_msg + (size_t)r * 64 + j0 + 1, h2);
        }
        if (lane < 24) {
            const int e = lane / 3;
            const int c = lane - e * 3;
            atomicAdd(g_coord + (size_t)idx[e] * 3 + c, rl[lane] * cwS[e]);
        }
    }
}

// ---------------------------------------------------------------------------
// Node kernel: warp per 4 nodes (unchanged).
// ---------------------------------------------------------------------------
__global__ __launch_bounds__(256, 2) void node_kernel(
    const float* __restrict__ h, const float* __restrict__ pos,
    const float* __restrict__ Wn1, const float* __restrict__ bn1,
    const float* __restrict__ Wn2, const float* __restrict__ bn2,
    float* __restrict__ hout, float* __restrict__ posout)
{
    extern __shared__ float sm[];
    float* Wn1s = sm;
    float* Wn2s = Wn1s + 128 * 64;
    float* bn1s = Wn2s + 64 * 64;
    float* bn2s = bn1s + 64;
    float* scr  = bn2s + 64;

    const int tid = threadIdx.x;
    for (int i = tid; i < 128 * 64; i += 256) Wn1s[i] = Wn1[i];
    for (int i = tid; i < 64 * 64; i += 256) Wn2s[i] = Wn2[i];
    if (tid < 64) { bn1s[tid] = bn1[tid]; bn2s[tid] = bn2[tid]; }
    __syncthreads();

    const int lane = tid & 31;
    const int w = tid >> 5;
    const int j0 = lane * 2;
    float* X = scr + w * 512;

    const int nTiles = N_NODES / 4;
    const int warpStride = gridDim.x * 8;

    for (int t = blockIdx.x * 8 + w; t < nTiles; t += warpStride) {
        __syncwarp();
        const int base = t * 4;
        #pragma unroll
        for (int e = 0; e < 4; e++) {
            const int n = base + e;
            ((float2*)(X + e * 128))[lane]      = ((const float2*)(h + (size_t)n * 64))[lane];
            ((float2*)(X + e * 128 + 64))[lane] = ((const float2*)(g_msg + (size_t)n * 64))[lane];
        }
        __syncwarp();

        float acc[4][2];
        {
            float b0 = bn1s[j0], b1 = bn1s[j0 + 1];
            #pragma unroll
            for (int e = 0; e < 4; e++) { acc[e][0] = b0; acc[e][1] = b1; }
        }
        #pragma unroll 2
        for (int k = 0; k < 128; k += 4) {
            float xv[4][4];
            #pragma unroll
            for (int e = 0; e < 4; e++) {
                float4 q = *(const float4*)(X + e * 128 + k);
                xv[e][0] = q.x; xv[e][1] = q.y; xv[e][2] = q.z; xv[e][3] = q.w;
            }
            #pragma unroll
            for (int kk = 0; kk < 4; kk++) {
                float2 wv = *(const float2*)(Wn1s + (k + kk) * 64 + j0);
                #pragma unroll
                for (int e = 0; e < 4; e++) {
                    acc[e][0] = fmaf(xv[e][kk], wv.x, acc[e][0]);
                    acc[e][1] = fmaf(xv[e][kk], wv.y, acc[e][1]);
                }
            }
        }
        __syncwarp();
        #pragma unroll
        for (int e = 0; e < 4; e++) {
            *(float2*)(X + e * 64 + j0) =
                make_float2(silu(acc[e][0]), silu(acc[e][1]));
        }
        __syncwarp();

        float acc2[4][2];
        {
            float b0 = bn2s[j0], b1 = bn2s[j0 + 1];
            #pragma unroll
            for (int e = 0; e < 4; e++) { acc2[e][0] = b0; acc2[e][1] = b1; }
        }
        #pragma unroll 2
        for (int k = 0; k < 64; k += 4) {
            float xv[4][4];
            #pragma unroll
            for (int e = 0; e < 4; e++) {
                float4 q = *(const float4*)(X + e * 64 + k);
                xv[e][0] = q.x; xv[e][1] = q.y; xv[e][2] = q.z; xv[e][3] = q.w;
            }
            #pragma unroll
            for (int kk = 0; kk < 4; kk++) {
                float2 wv = *(const float2*)(Wn2s + (k + kk) * 64 + j0);
                #pragma unroll
                for (int e = 0; e < 4; e++) {
                    acc2[e][0] = fmaf(xv[e][kk], wv.x, acc2[e][0]);
                    acc2[e][1] = fmaf(xv[e][kk], wv.y, acc2[e][1]);
                }
            }
        }
        #pragma unroll
        for (int e = 0; e < 4; e++) {
            const int n = base + e;
            ((float2*)(hout + (size_t)n * 64))[lane] =
                make_float2(acc2[e][0], acc2[e][1]);
        }
        if (lane < 12) {
            const int e = lane / 3;
            const int c = lane - e * 3;
            const int n = base + e;
            posout[n * 3 + c] = pos[n * 3 + c] + g_coord[n * 3 + c];
        }
    }
}

// ---------------------------------------------------------------------------
extern "C" void kernel_launch(void* const* d_in, const int* in_sizes, int n_in,
                              void* d_out, int out_size)
{
    const float* h   = (const float*)d_in[0];
    const float* pos = (const float*)d_in[1];
    const unsigned int* ei_words = (const unsigned int*)d_in[2];
    const float* We1 = (const float*)d_in[3];
    const float* be1 = (const float*)d_in[4];
    const float* We2 = (const float*)d_in[5];
    const float* be2 = (const float*)d_in[6];
    const float* Wc1 = (const float*)d_in[7];
    const float* bc1 = (const float*)d_in[8];
    const float* Wc2 = (const float*)d_in[9];
    const float* bc2 = (const float*)d_in[10];
    const float* Wn1 = (const float*)d_in[11];
    const float* bn1 = (const float*)d_in[12];
    const float* Wn2 = (const float*)d_in[13];
    const float* bn2 = (const float*)d_in[14];

    float* hout   = (float*)d_out;
    float* posout = hout + (size_t)N_NODES * 64;

    void* msgPtr = nullptr;
    void* coordPtr = nullptr;
    cudaGetSymbolAddress(&msgPtr, g_msg);
    cudaGetSymbolAddress(&coordPtr, g_coord);
    cudaMemsetAsync(msgPtr, 0, sizeof(float) * (size_t)N_NODES * 64);
    cudaMemsetAsync(coordPtr, 0, sizeof(float) * (size_t)N_NODES * 3);

    decode_edges<<<1024, 256>>>(ei_words);

    const int PROJ_SMEM = (128 * 64 + 8 * 256) * 4;
    const int EDGE_SMEM = (2 * 64 * 64 + 5 * 64 + EWARPS * WSCR) * 4;
    const int NODE_SMEM = (128 * 64 + 64 * 64 + 2 * 64 + 8 * 512) * 4;

    cudaFuncSetAttribute(proj_kernel, cudaFuncAttributeMaxDynamicSharedMemorySize, PROJ_SMEM);
    cudaFuncSetAttribute(edge_kernel, cudaFuncAttributeMaxDynamicSharedMemorySize, EDGE_SMEM);
    cudaFuncSetAttribute(node_kernel, cudaFuncAttributeMaxDynamicSharedMemorySize, NODE_SMEM);

    proj_kernel<<<304, 256, PROJ_SMEM>>>(h, We1);
    edge_kernel<<<148, EWARPS * 32, EDGE_SMEM>>>(pos,
                                                 We1, be1, We2, be2,
                                                 Wc1, bc1, Wc2, bc2);
    node_kernel<<<304, 256, NODE_SMEM>>>(h, pos, Wn1, bn1, Wn2, bn2,
                                         hout, posout);
}

// round 14
// speedup vs baseline: 1.4689x; 1.0474x over previous
#include <cuda_runtime.h>

#define N_NODES 50000
#define N_EDGES 800000

#define EB 8                      // edges per warp-tile
#define NTILES (N_EDGES / EB)     // 100000
#define EWARPS 20                 // warps per edge-kernel CTA
#define XSTR 20                   // padded row stride (floats) in Xm
#define WSCR 1360                 // per-warp scratch floats

// Device-global scratch (allocation rules forbid cudaMalloc)
__device__ float g_msg[N_NODES * 64];
__device__ float g_coord[N_NODES * 3];
__device__ float g_pa[N_NODES * 64];      // h @ We1[0:64]
__device__ float g_pb[N_NODES * 64];      // h @ We1[64:128]
__device__ int   g_row[N_EDGES];
__device__ int   g_col[N_EDGES];

__device__ __forceinline__ float silu(float x) {
    return x * (1.0f / (1.0f + __expf(-x)));
}

// ---- packed fp32x2 helpers --------------------------------------------------
__device__ __forceinline__ unsigned long long pack2(float lo, float hi) {
    unsigned long long r;
    asm("mov.b64 %0, {%1, %2};" : "=l"(r) : "f"(lo), "f"(hi));
    return r;
}
__device__ __forceinline__ void unpack2(unsigned long long p, float& lo, float& hi) {
    asm("mov.b64 {%0, %1}, %2;" : "=f"(lo), "=f"(hi) : "l"(p));
}
__device__ __forceinline__ void ffma2(unsigned long long& d,
                                      unsigned long long a,
                                      unsigned long long b) {
    asm("fma.rn.f32x2 %0, %1, %2, %0;" : "+l"(d) : "l"(a), "l"(b));
}
__device__ __forceinline__ unsigned long long add2(unsigned long long a,
                                                   unsigned long long b) {
    unsigned long long r;
    asm("add.rn.f32x2 %0, %1, %2;" : "=l"(r) : "l"(a), "l"(b));
    return r;
}
// vector reduction: one 8B red per lane instead of two 4B atomics
__device__ __forceinline__ void red_add_v2(float* ptr, float lo, float hi) {
    asm volatile("red.global.add.v2.f32 [%0], {%1, %2};"
                 :: "l"(ptr), "f"(lo), "f"(hi) : "memory");
}

// ---------------------------------------------------------------------------
// Decode edge_index (reference claims int64; JAX x64-off emits int32 — detect).
// ---------------------------------------------------------------------------
__global__ void decode_edges(const unsigned int* __restrict__ w) {
    __shared__ int is64_s;
    if (threadIdx.x == 0) {
        int is64 = 1;
        #pragma unroll 1
        for (int i = 1; i < 128; i += 2)
            if (w[i] != 0u) { is64 = 0; break; }
        is64_s = is64;
    }
    __syncthreads();
    const int is64 = is64_s;
    const int total = 2 * N_EDGES;
    for (int i = blockIdx.x * blockDim.x + threadIdx.x; i < total;
         i += gridDim.x * blockDim.x) {
        int v = is64 ? (int)w[2 * i] : (int)w[i];
        v = max(0, min(v, N_NODES - 1));
        if (i < N_EDGES) g_row[i] = v;
        else             g_col[i - N_EDGES] = v;
    }
}

// ---------------------------------------------------------------------------
// Projection kernel: P_a = h @ We1[0:64], P_b = h @ We1[64:128].
// ---------------------------------------------------------------------------
__global__ __launch_bounds__(256, 2) void proj_kernel(
    const float* __restrict__ h, const float* __restrict__ We1)
{
    extern __shared__ float sm[];
    float* Ws  = sm;                 // 128*64
    float* scr = Ws + 128 * 64;      // 8 warps * 256

    const int tid = threadIdx.x;
    for (int i = tid; i < 128 * 64; i += 256) Ws[i] = We1[i];
    __syncthreads();

    const int lane = tid & 31;
    const int w = tid >> 5;
    const int j0 = lane * 2;
    float* X = scr + w * 256;

    const int nTiles = N_NODES / 4;
    const int warpStride = gridDim.x * 8;

    for (int t = blockIdx.x * 8 + w; t < nTiles; t += warpStride) {
        __syncwarp();
        const int base = t * 4;
        #pragma unroll
        for (int e = 0; e < 4; e++)
            ((float2*)(X + e * 64))[lane] = ((const float2*)(h + (size_t)(base + e) * 64))[lane];
        __syncwarp();

        float pa[4][2], pb[4][2];
        #pragma unroll
        for (int e = 0; e < 4; e++) {
            pa[e][0] = 0.f; pa[e][1] = 0.f; pb[e][0] = 0.f; pb[e][1] = 0.f;
        }
        #pragma unroll 2
        for (int k = 0; k < 64; k += 4) {
            float xv[4][4];
            #pragma unroll
            for (int e = 0; e < 4; e++) {
                float4 q = *(const float4*)(X + e * 64 + k);
                xv[e][0] = q.x; xv[e][1] = q.y; xv[e][2] = q.z; xv[e][3] = q.w;
            }
            #pragma unroll
            for (int kk = 0; kk < 4; kk++) {
                float2 wa = *(const float2*)(Ws + (k + kk) * 64 + j0);
                float2 wb = *(const float2*)(Ws + (64 + k + kk) * 64 + j0);
                #pragma unroll
                for (int e = 0; e < 4; e++) {
                    pa[e][0] = fmaf(xv[e][kk], wa.x, pa[e][0]);
                    pa[e][1] = fmaf(xv[e][kk], wa.y, pa[e][1]);
                    pb[e][0] = fmaf(xv[e][kk], wb.x, pb[e][0]);
                    pb[e][1] = fmaf(xv[e][kk], wb.y, pb[e][1]);
                }
            }
        }
        #pragma unroll
        for (int e = 0; e < 4; e++) {
            const int n = base + e;
            ((float2*)(g_pa + (size_t)n * 64))[lane] = make_float2(pa[e][0], pa[e][1]);
            ((float2*)(g_pb + (size_t)n * 64))[lane] = make_float2(pb[e][0], pb[e][1]);
        }
    }
}

// ---------------------------------------------------------------------------
// Edge kernel v5: factored layer1; FFMA2 loops; em kept in regs for scatter
// (correct per-edge (col j0, col j0+1) pairing); g_msg scatter via
// red.global.add.v2.f32.
// ---------------------------------------------------------------------------
__global__ __launch_bounds__(EWARPS * 32, 1) void edge_kernel(
    const float* __restrict__ pos,
    const float* __restrict__ We1, const float* __restrict__ be1,
    const float* __restrict__ We2, const float* __restrict__ be2,
    const float* __restrict__ Wc1, const float* __restrict__ bc1,
    const float* __restrict__ Wc2, const float* __restrict__ bc2)
{
    extern __shared__ float sm[];
    float* We2s = sm;                  // 4096
    float* Wc1s = We2s + 64 * 64;      // 4096
    float* wdss = Wc1s + 64 * 64;      // 64
    float* be1s = wdss + 64;           // 64
    float* be2s = be1s + 64;           // 64
    float* bc1s = be2s + 64;           // 64
    float* Wc2s = bc1s + 64;           // 64
    float* scr  = Wc2s + 64;           // EWARPS * WSCR

    const int tid = threadIdx.x;
    const int nthr = EWARPS * 32;
    for (int i = tid; i < 64 * 64; i += nthr) { We2s[i] = We2[i]; Wc1s[i] = Wc1[i]; }
    if (tid < 64) {
        wdss[tid] = We1[128 * 64 + tid];
        be1s[tid] = be1[tid]; be2s[tid] = be2[tid];
        bc1s[tid] = bc1[tid]; Wc2s[tid] = Wc2[tid];
    }
    __syncthreads();

    const float bc2v = __ldg(bc2);
    const int lane = tid & 31;
    const int w    = tid >> 5;
    const int j0   = lane * 2;

    float* Xm  = scr + w * WSCR;        // 64 rows * XSTR = 1280
    float* rl  = Xm + 64 * XSTR;        // 24
    float* cwS = rl + 24;               // 8
    unsigned long long* ds2 = (unsigned long long*)(cwS + 8);  // 8 u64
    int* idx = (int*)(ds2 + 8);         // 16

    const unsigned long long be1p = *(const unsigned long long*)(be1s + j0);
    const unsigned long long be2p = *(const unsigned long long*)(be2s + j0);
    const unsigned long long bc1p = *(const unsigned long long*)(bc1s + j0);
    const unsigned long long wdsp = *(const unsigned long long*)(wdss + j0);
    const float wc2_0 = Wc2s[j0], wc2_1 = Wc2s[j0 + 1];

    const int warpStride = gridDim.x * EWARPS;

    for (int t = blockIdx.x * EWARPS + w; t < NTILES; t += warpStride) {
        __syncwarp();
        const int base = t * EB;
        if (lane < EB) {
            idx[lane]      = g_row[base + lane];
            idx[EB + lane] = g_col[base + lane];
        }
        __syncwarp();

        // ---- gather projections (L2-resident), rel_pos/ds by lanes 0..7
        float2 pa[EB], pb[EB];
        #pragma unroll
        for (int e = 0; e < EB; e++) {
            pa[e] = *(const float2*)(g_pa + (size_t)idx[e] * 64 + j0);
            pb[e] = *(const float2*)(g_pb + (size_t)idx[EB + e] * 64 + j0);
        }
        if (lane < EB) {
            const int e = lane;
            const int r = idx[e], c = idx[EB + e];
            float dx = pos[r * 3 + 0] - pos[c * 3 + 0];
            float dy = pos[r * 3 + 1] - pos[c * 3 + 1];
            float dz = pos[r * 3 + 2] - pos[c * 3 + 2];
            rl[e * 3 + 0] = dx; rl[e * 3 + 1] = dy; rl[e * 3 + 2] = dz;
            float ds = dx * dx + dy * dy + dz * dz;
            ds2[e] = pack2(ds, ds);
        }
        __syncwarp();

        // ---- layer 1 (factored): silu(pa + pb + ds*wds + b) -> m, dup'd to Xm
        #pragma unroll
        for (int p = 0; p < 4; p++) {
            float v0l, v0h, v1l, v1h;
            {
                unsigned long long a = add2(pack2(pa[2 * p].x + pb[2 * p].x,
                                                  pa[2 * p].y + pb[2 * p].y), be1p);
                ffma2(a, ds2[2 * p], wdsp);
                float lo, hi; unpack2(a, lo, hi);
                v0l = silu(lo); v0h = silu(hi);
            }
            {
                unsigned long long a = add2(pack2(pa[2 * p + 1].x + pb[2 * p + 1].x,
                                                  pa[2 * p + 1].y + pb[2 * p + 1].y), be1p);
                ffma2(a, ds2[2 * p + 1], wdsp);
                float lo, hi; unpack2(a, lo, hi);
                v1l = silu(lo); v1h = silu(hi);
            }
            *(float4*)(Xm + j0 * XSTR + 4 * p)       = make_float4(v0l, v0l, v1l, v1l);
            *(float4*)(Xm + (j0 + 1) * XSTR + 4 * p) = make_float4(v0h, v0h, v1h, v1h);
        }
        __syncwarp();

        // ---- layer 2: (64 -> 64), SiLU -> edge_msg
        unsigned long long acc[EB];
        #pragma unroll
        for (int e = 0; e < EB; e++) acc[e] = be2p;
        #pragma unroll 4
        for (int k = 0; k < 64; k++) {
            const float* row = Xm + k * XSTR;
            ulonglong2 q01 = *(const ulonglong2*)(row);
            ulonglong2 q23 = *(const ulonglong2*)(row + 4);
            ulonglong2 q45 = *(const ulonglong2*)(row + 8);
            ulonglong2 q67 = *(const ulonglong2*)(row + 12);
            unsigned long long wp = *(const unsigned long long*)(We2s + k * 64 + j0);
            ffma2(acc[0], q01.x, wp); ffma2(acc[1], q01.y, wp);
            ffma2(acc[2], q23.x, wp); ffma2(acc[3], q23.y, wp);
            ffma2(acc[4], q45.x, wp); ffma2(acc[5], q45.y, wp);
            ffma2(acc[6], q67.x, wp); ffma2(acc[7], q67.y, wp);
        }
        __syncwarp();   // everyone done reading m before overwrite with em
        // em[e] = edge e's (col j0, col j0+1) — kept in regs for the scatter.
        // acc[e] already IS edge e's (col j0, col j0+1): just silu both halves.
        unsigned long long em[EB];
        #pragma unroll
        for (int p = 0; p < 4; p++) {
            float l0, h0, l1, h1;
            unpack2(acc[2 * p], l0, h0);       // edge 2p:   l0=col j0, h0=col j0+1
            unpack2(acc[2 * p + 1], l1, h1);   // edge 2p+1: l1=col j0, h1=col j0+1
            l0 = silu(l0); h0 = silu(h0); l1 = silu(l1); h1 = silu(h1);
            em[2 * p]     = pack2(l0, h0);     // edge 2p   (col j0, col j0+1)
            em[2 * p + 1] = pack2(l1, h1);     // edge 2p+1 (col j0, col j0+1)
            // Xm rows are per-feature, duplicated per edge-pair:
            // row j0:   (e2p, e2p, e2p+1, e2p+1) of col j0
            // row j0+1: same of col j0+1
            *(float4*)(Xm + j0 * XSTR + 4 * p)       = make_float4(l0, l0, l1, l1);
            *(float4*)(Xm + (j0 + 1) * XSTR + 4 * p) = make_float4(h0, h0, h1, h1);
        }
        __syncwarp();

        // ---- coord MLP layer 1: (64 -> 64), SiLU
        unsigned long long acc3[EB];
        #pragma unroll
        for (int e = 0; e < EB; e++) acc3[e] = bc1p;
        #pragma unroll 4
        for (int k = 0; k < 64; k++) {
            const float* row = Xm + k * XSTR;
            ulonglong2 q01 = *(const ulonglong2*)(row);
            ulonglong2 q23 = *(const ulonglong2*)(row + 4);
            ulonglong2 q45 = *(const ulonglong2*)(row + 8);
            ulonglong2 q67 = *(const ulonglong2*)(row + 12);
            unsigned long long wp = *(const unsigned long long*)(Wc1s + k * 64 + j0);
            ffma2(acc3[0], q01.x, wp); ffma2(acc3[1], q01.y, wp);
            ffma2(acc3[2], q23.x, wp); ffma2(acc3[3], q23.y, wp);
            ffma2(acc3[4], q45.x, wp); ffma2(acc3[5], q45.y, wp);
            ffma2(acc3[6], q67.x, wp); ffma2(acc3[7], q67.y, wp);
        }
        // ---- coord MLP layer 2: (64 -> 1), warp reduction per edge
        #pragma unroll
        for (int e = 0; e < EB; e++) {
            float lo, hi; unpack2(acc3[e], lo, hi);
            float v = fmaf(silu(lo), wc2_0, silu(hi) * wc2_1);
            v += __shfl_xor_sync(0xffffffffu, v, 16);
            v += __shfl_xor_sync(0xffffffffu, v, 8);
            v += __shfl_xor_sync(0xffffffffu, v, 4);
            v += __shfl_xor_sync(0xffffffffu, v, 2);
            v += __shfl_xor_sync(0xffffffffu, v, 1);
            if (lane == 0) cwS[e] = v + bc2v;
        }
        __syncwarp();

        // ---- scatter: one vector RED per lane per edge (em from regs)
        #pragma unroll
        for (int e = 0; e < EB; e++) {
            float lo, hi; unpack2(em[e], lo, hi);
            red_add_v2(g_msg + (size_t)idx[e] * 64 + j0, lo, hi);
        }
        if (lane < 24) {
            const int e = lane / 3;
            const int c = lane - e * 3;
            atomicAdd(g_coord + (size_t)idx[e] * 3 + c, rl[lane] * cwS[e]);
        }
    }
}

// ---------------------------------------------------------------------------
// Node kernel: warp per 4 nodes (unchanged).
// ---------------------------------------------------------------------------
__global__ __launch_bounds__(256, 2) void node_kernel(
    const float* __restrict__ h, const float* __restrict__ pos,
    const float* __restrict__ Wn1, const float* __restrict__ bn1,
    const float* __restrict__ Wn2, const float* __restrict__ bn2,
    float* __restrict__ hout, float* __restrict__ posout)
{
    extern __shared__ float sm[];
    float* Wn1s = sm;
    float* Wn2s = Wn1s + 128 * 64;
    float* bn1s = Wn2s + 64 * 64;
    float* bn2s = bn1s + 64;
    float* scr  = bn2s + 64;

    const int tid = threadIdx.x;
    for (int i = tid; i < 128 * 64; i += 256) Wn1s[i] = Wn1[i];
    for (int i = tid; i < 64 * 64; i += 256) Wn2s[i] = Wn2[i];
    if (tid < 64) { bn1s[tid] = bn1[tid]; bn2s[tid] = bn2[tid]; }
    __syncthreads();

    const int lane = tid & 31;
    const int w = tid >> 5;
    const int j0 = lane * 2;
    float* X = scr + w * 512;

    const int nTiles = N_NODES / 4;
    const int warpStride = gridDim.x * 8;

    for (int t = blockIdx.x * 8 + w; t < nTiles; t += warpStride) {
        __syncwarp();
        const int base = t * 4;
        #pragma unroll
        for (int e = 0; e < 4; e++) {
            const int n = base + e;
            ((float2*)(X + e * 128))[lane]      = ((const float2*)(h + (size_t)n * 64))[lane];
            ((float2*)(X + e * 128 + 64))[lane] = ((const float2*)(g_msg + (size_t)n * 64))[lane];
        }
        __syncwarp();

        float acc[4][2];
        {
            float b0 = bn1s[j0], b1 = bn1s[j0 + 1];
            #pragma unroll
            for (int e = 0; e < 4; e++) { acc[e][0] = b0; acc[e][1] = b1; }
        }
        #pragma unroll 2
        for (int k = 0; k < 128; k += 4) {
            float xv[4][4];
            #pragma unroll
            for (int e = 0; e < 4; e++) {
                float4 q = *(const float4*)(X + e * 128 + k);
                xv[e][0] = q.x; xv[e][1] = q.y; xv[e][2] = q.z; xv[e][3] = q.w;
            }
            #pragma unroll
            for (int kk = 0; kk < 4; kk++) {
                float2 wv = *(const float2*)(Wn1s + (k + kk) * 64 + j0);
                #pragma unroll
                for (int e = 0; e < 4; e++) {
                    acc[e][0] = fmaf(xv[e][kk], wv.x, acc[e][0]);
                    acc[e][1] = fmaf(xv[e][kk], wv.y, acc[e][1]);
                }
            }
        }
        __syncwarp();
        #pragma unroll
        for (int e = 0; e < 4; e++) {
            *(float2*)(X + e * 64 + j0) =
                make_float2(silu(acc[e][0]), silu(acc[e][1]));
        }
        __syncwarp();

        float acc2[4][2];
        {
            float b0 = bn2s[j0], b1 = bn2s[j0 + 1];
            #pragma unroll
            for (int e = 0; e < 4; e++) { acc2[e][0] = b0; acc2[e][1] = b1; }
        }
        #pragma unroll 2
        for (int k = 0; k < 64; k += 4) {
            float xv[4][4];
            #pragma unroll
            for (int e = 0; e < 4; e++) {
                float4 q = *(const float4*)(X + e * 64 + k);
                xv[e][0] = q.x; xv[e][1] = q.y; xv[e][2] = q.z; xv[e][3] = q.w;
            }
            #pragma unroll
            for (int kk = 0; kk < 4; kk++) {
                float2 wv = *(const float2*)(Wn2s + (k + kk) * 64 + j0);
                #pragma unroll
                for (int e = 0; e < 4; e++) {
                    acc2[e][0] = fmaf(xv[e][kk], wv.x, acc2[e][0]);
                    acc2[e][1] = fmaf(xv[e][kk], wv.y, acc2[e][1]);
                }
            }
        }
        #pragma unroll
        for (int e = 0; e < 4; e++) {
            const int n = base + e;
            ((float2*)(hout + (size_t)n * 64))[lane] =
                make_float2(acc2[e][0], acc2[e][1]);
        }
        if (lane < 12) {
            const int e = lane / 3;
            const int c = lane - e * 3;
            const int n = base + e;
            posout[n * 3 + c] = pos[n * 3 + c] + g_coord[n * 3 + c];
        }
    }
}

// ---------------------------------------------------------------------------
extern "C" void kernel_launch(void* const* d_in, const int* in_sizes, int n_in,
                              void* d_out, int out_size)
{
    const float* h   = (const float*)d_in[0];
    const float* pos = (const float*)d_in[1];
    const unsigned int* ei_words = (const unsigned int*)d_in[2];
    const float* We1 = (const float*)d_in[3];
    const float* be1 = (const float*)d_in[4];
    const float* We2 = (const float*)d_in[5];
    const float* be2 = (const float*)d_in[6];
    const float* Wc1 = (const float*)d_in[7];
    const float* bc1 = (const float*)d_in[8];
    const float* Wc2 = (const float*)d_in[9];
    const float* bc2 = (const float*)d_in[10];
    const float* Wn1 = (const float*)d_in[11];
    const float* bn1 = (const float*)d_in[12];
    const float* Wn2 = (const float*)d_in[13];
    const float* bn2 = (const float*)d_in[14];

    float* hout   = (float*)d_out;
    float* posout = hout + (size_t)N_NODES * 64;

    void* msgPtr = nullptr;
    void* coordPtr = nullptr;
    cudaGetSymbolAddress(&msgPtr, g_msg);
    cudaGetSymbolAddress(&coordPtr, g_coord);
    cudaMemsetAsync(msgPtr, 0, sizeof(float) * (size_t)N_NODES * 64);
    cudaMemsetAsync(coordPtr, 0, sizeof(float) * (size_t)N_NODES * 3);

    decode_edges<<<1024, 256>>>(ei_words);

    const int PROJ_SMEM = (128 * 64 + 8 * 256) * 4;
    const int EDGE_SMEM = (2 * 64 * 64 + 5 * 64 + EWARPS * WSCR) * 4;
    const int NODE_SMEM = (128 * 64 + 64 * 64 + 2 * 64 + 8 * 512) * 4;

    cudaFuncSetAttribute(proj_kernel, cudaFuncAttributeMaxDynamicSharedMemorySize, PROJ_SMEM);
    cudaFuncSetAttribute(edge_kernel, cudaFuncAttributeMaxDynamicSharedMemorySize, EDGE_SMEM);
    cudaFuncSetAttribute(node_kernel, cudaFuncAttributeMaxDynamicSharedMemorySize, NODE_SMEM);

    proj_kernel<<<304, 256, PROJ_SMEM>>>(h, We1);
    edge_kernel<<<148, EWARPS * 32, EDGE_SMEM>>>(pos,
                                                 We1, be1, We2, be2,
                                                 Wc1, bc1, Wc2, bc2);
    node_kernel<<<304, 256, NODE_SMEM>>>(h, pos, Wn1, bn1, Wn2, bn2,
                                         hout, posout);
}

// round 15
// speedup vs baseline: 1.5076x; 1.0263x over previous
#include <cuda_runtime.h>

#define N_NODES 50000
#define N_EDGES 800000

#define EB 8                      // edges per warp-tile
#define NTILES (N_EDGES / EB)     // 100000
#define EWARPS 20                 // warps per edge-kernel CTA
#define XSTR 20                   // padded row stride (floats) in Xm
#define WSCR 1360                 // per-warp scratch floats

// Device-global scratch (allocation rules forbid cudaMalloc)
__device__ float g_msg[N_NODES * 64];
__device__ float g_coord[N_NODES * 3];
__device__ float g_pa[N_NODES * 64];      // h @ We1[0:64]
__device__ float g_pb[N_NODES * 64];      // h @ We1[64:128]
__device__ int   g_row[N_EDGES];
__device__ int   g_col[N_EDGES];

__device__ __forceinline__ float silu(float x) {
    return x * (1.0f / (1.0f + __expf(-x)));
}

// ---- packed fp32x2 helpers --------------------------------------------------
__device__ __forceinline__ unsigned long long pack2(float lo, float hi) {
    unsigned long long r;
    asm("mov.b64 %0, {%1, %2};" : "=l"(r) : "f"(lo), "f"(hi));
    return r;
}
__device__ __forceinline__ void unpack2(unsigned long long p, float& lo, float& hi) {
    asm("mov.b64 {%0, %1}, %2;" : "=f"(lo), "=f"(hi) : "l"(p));
}
__device__ __forceinline__ void ffma2(unsigned long long& d,
                                      unsigned long long a,
                                      unsigned long long b) {
    asm("fma.rn.f32x2 %0, %1, %2, %0;" : "+l"(d) : "l"(a), "l"(b));
}
__device__ __forceinline__ unsigned long long add2(unsigned long long a,
                                                   unsigned long long b) {
    unsigned long long r;
    asm("add.rn.f32x2 %0, %1, %2;" : "=l"(r) : "l"(a), "l"(b));
    return r;
}
// vector reduction: one 8B red per lane instead of two 4B atomics
__device__ __forceinline__ void red_add_v2(float* ptr, float lo, float hi) {
    asm volatile("red.global.add.v2.f32 [%0], {%1, %2};"
                 :: "l"(ptr), "f"(lo), "f"(hi) : "memory");
}

// ---------------------------------------------------------------------------
// Empty kernel: shifts ncu's capture slot (-s 5 -c 1) so launch #6 is the
// edge kernel instead of node/decode. ~2us cost.
// ---------------------------------------------------------------------------
__global__ void align_dummy() {}

// ---------------------------------------------------------------------------
// Decode edge_index (reference claims int64; JAX x64-off emits int32 — detect).
// ---------------------------------------------------------------------------
__global__ void decode_edges(const unsigned int* __restrict__ w) {
    __shared__ int is64_s;
    if (threadIdx.x == 0) {
        int is64 = 1;
        #pragma unroll 1
        for (int i = 1; i < 128; i += 2)
            if (w[i] != 0u) { is64 = 0; break; }
        is64_s = is64;
    }
    __syncthreads();
    const int is64 = is64_s;
    const int total = 2 * N_EDGES;
    for (int i = blockIdx.x * blockDim.x + threadIdx.x; i < total;
         i += gridDim.x * blockDim.x) {
        int v = is64 ? (int)w[2 * i] : (int)w[i];
        v = max(0, min(v, N_NODES - 1));
        if (i < N_EDGES) g_row[i] = v;
        else             g_col[i - N_EDGES] = v;
    }
}

// ---------------------------------------------------------------------------
// Projection kernel: P_a = h @ We1[0:64], P_b = h @ We1[64:128].
// ---------------------------------------------------------------------------
__global__ __launch_bounds__(256, 2) void proj_kernel(
    const float* __restrict__ h, const float* __restrict__ We1)
{
    extern __shared__ float sm[];
    float* Ws  = sm;                 // 128*64
    float* scr = Ws + 128 * 64;      // 8 warps * 256

    const int tid = threadIdx.x;
    for (int i = tid; i < 128 * 64; i += 256) Ws[i] = We1[i];
    __syncthreads();

    const int lane = tid & 31;
    const int w = tid >> 5;
    const int j0 = lane * 2;
    float* X = scr + w * 256;

    const int nTiles = N_NODES / 4;
    const int warpStride = gridDim.x * 8;

    for (int t = blockIdx.x * 8 + w; t < nTiles; t += warpStride) {
        __syncwarp();
        const int base = t * 4;
        #pragma unroll
        for (int e = 0; e < 4; e++)
            ((float2*)(X + e * 64))[lane] = ((const float2*)(h + (size_t)(base + e) * 64))[lane];
        __syncwarp();

        float pa[4][2], pb[4][2];
        #pragma unroll
        for (int e = 0; e < 4; e++) {
            pa[e][0] = 0.f; pa[e][1] = 0.f; pb[e][0] = 0.f; pb[e][1] = 0.f;
        }
        #pragma unroll 2
        for (int k = 0; k < 64; k += 4) {
            float xv[4][4];
            #pragma unroll
            for (int e = 0; e < 4; e++) {
                float4 q = *(const float4*)(X + e * 64 + k);
                xv[e][0] = q.x; xv[e][1] = q.y; xv[e][2] = q.z; xv[e][3] = q.w;
            }
            #pragma unroll
            for (int kk = 0; kk < 4; kk++) {
                float2 wa = *(const float2*)(Ws + (k + kk) * 64 + j0);
                float2 wb = *(const float2*)(Ws + (64 + k + kk) * 64 + j0);
                #pragma unroll
                for (int e = 0; e < 4; e++) {
                    pa[e][0] = fmaf(xv[e][kk], wa.x, pa[e][0]);
                    pa[e][1] = fmaf(xv[e][kk], wa.y, pa[e][1]);
                    pb[e][0] = fmaf(xv[e][kk], wb.x, pb[e][0]);
                    pb[e][1] = fmaf(xv[e][kk], wb.y, pb[e][1]);
                }
            }
        }
        #pragma unroll
        for (int e = 0; e < 4; e++) {
            const int n = base + e;
            ((float2*)(g_pa + (size_t)n * 64))[lane] = make_float2(pa[e][0], pa[e][1]);
            ((float2*)(g_pb + (size_t)n * 64))[lane] = make_float2(pb[e][0], pb[e][1]);
        }
    }
}

// ---------------------------------------------------------------------------
// Edge kernel v6: chunk-rotation swizzle on Xm rows kills the 8-way STS bank
// conflicts of v5. Physical chunk of logical 16B-chunk p in row r is
// ((p + (r>>3)) & 3). Store side: rotation is loop-invariant per lane (rows
// j0=2*lane, j0+1 share r>>3 = lane>>2) -> precomputed pointers. Load side:
// k-loops run as 8 outer x 8 inner with rotation constant per outer step.
// ---------------------------------------------------------------------------
__global__ __launch_bounds__(EWARPS * 32, 1) void edge_kernel(
    const float* __restrict__ pos,
    const float* __restrict__ We1, const float* __restrict__ be1,
    const float* __restrict__ We2, const float* __restrict__ be2,
    const float* __restrict__ Wc1, const float* __restrict__ bc1,
    const float* __restrict__ Wc2, const float* __restrict__ bc2)
{
    extern __shared__ float sm[];
    float* We2s = sm;                  // 4096
    float* Wc1s = We2s + 64 * 64;      // 4096
    float* wdss = Wc1s + 64 * 64;      // 64
    float* be1s = wdss + 64;           // 64
    float* be2s = be1s + 64;           // 64
    float* bc1s = be2s + 64;           // 64
    float* Wc2s = bc1s + 64;           // 64
    float* scr  = Wc2s + 64;           // EWARPS * WSCR

    const int tid = threadIdx.x;
    const int nthr = EWARPS * 32;
    for (int i = tid; i < 64 * 64; i += nthr) { We2s[i] = We2[i]; Wc1s[i] = Wc1[i]; }
    if (tid < 64) {
        wdss[tid] = We1[128 * 64 + tid];
        be1s[tid] = be1[tid]; be2s[tid] = be2[tid];
        bc1s[tid] = bc1[tid]; Wc2s[tid] = Wc2[tid];
    }
    __syncthreads();

    const float bc2v = __ldg(bc2);
    const int lane = tid & 31;
    const int w    = tid >> 5;
    const int j0   = lane * 2;

    float* Xm  = scr + w * WSCR;        // 64 rows * XSTR = 1280
    float* rl  = Xm + 64 * XSTR;        // 24
    float* cwS = rl + 24;               // 8
    unsigned long long* ds2 = (unsigned long long*)(cwS + 8);  // 8 u64
    int* idx = (int*)(ds2 + 8);         // 16

    // Swizzled store pointers: rows j0, j0+1 have rotation (lane>>2)&3.
    const int rotW = (lane >> 2) & 3;
    float* st0[4]; float* st1[4];
    #pragma unroll
    for (int p = 0; p < 4; p++) {
        const int phys = ((p + rotW) & 3) * 4;
        st0[p] = Xm + j0 * XSTR + phys;
        st1[p] = Xm + (j0 + 1) * XSTR + phys;
    }

    const unsigned long long be1p = *(const unsigned long long*)(be1s + j0);
    const unsigned long long be2p = *(const unsigned long long*)(be2s + j0);
    const unsigned long long bc1p = *(const unsigned long long*)(bc1s + j0);
    const unsigned long long wdsp = *(const unsigned long long*)(wdss + j0);
    const float wc2_0 = Wc2s[j0], wc2_1 = Wc2s[j0 + 1];

    const int warpStride = gridDim.x * EWARPS;

    for (int t = blockIdx.x * EWARPS + w; t < NTILES; t += warpStride) {
        __syncwarp();
        const int base = t * EB;
        if (lane < EB) {
            idx[lane]      = g_row[base + lane];
            idx[EB + lane] = g_col[base + lane];
        }
        __syncwarp();

        // ---- gather projections (L2-resident), rel_pos/ds by lanes 0..7
        float2 pa[EB], pb[EB];
        #pragma unroll
        for (int e = 0; e < EB; e++) {
            pa[e] = *(const float2*)(g_pa + (size_t)idx[e] * 64 + j0);
            pb[e] = *(const float2*)(g_pb + (size_t)idx[EB + e] * 64 + j0);
        }
        if (lane < EB) {
            const int e = lane;
            const int r = idx[e], c = idx[EB + e];
            float dx = pos[r * 3 + 0] - pos[c * 3 + 0];
            float dy = pos[r * 3 + 1] - pos[c * 3 + 1];
            float dz = pos[r * 3 + 2] - pos[c * 3 + 2];
            rl[e * 3 + 0] = dx; rl[e * 3 + 1] = dy; rl[e * 3 + 2] = dz;
            float ds = dx * dx + dy * dy + dz * dz;
            ds2[e] = pack2(ds, ds);
        }
        __syncwarp();

        // ---- layer 1 (factored): silu(pa + pb + ds*wds + b) -> m, dup'd to Xm
        #pragma unroll
        for (int p = 0; p < 4; p++) {
            float v0l, v0h, v1l, v1h;
            {
                unsigned long long a = add2(pack2(pa[2 * p].x + pb[2 * p].x,
                                                  pa[2 * p].y + pb[2 * p].y), be1p);
                ffma2(a, ds2[2 * p], wdsp);
                float lo, hi; unpack2(a, lo, hi);
                v0l = silu(lo); v0h = silu(hi);
            }
            {
                unsigned long long a = add2(pack2(pa[2 * p + 1].x + pb[2 * p + 1].x,
                                                  pa[2 * p + 1].y + pb[2 * p + 1].y), be1p);
                ffma2(a, ds2[2 * p + 1], wdsp);
                float lo, hi; unpack2(a, lo, hi);
                v1l = silu(lo); v1h = silu(hi);
            }
            *(float4*)st0[p] = make_float4(v0l, v0l, v1l, v1l);
            *(float4*)st1[p] = make_float4(v0h, v0h, v1h, v1h);
        }
        __syncwarp();

        // ---- layer 2: (64 -> 64), SiLU -> edge_msg
        unsigned long long acc[EB];
        #pragma unroll
        for (int e = 0; e < EB; e++) acc[e] = be2p;
        #pragma unroll 1
        for (int a = 0; a < 8; a++) {
            const int rr = a & 3;
            const int o0 = ((0 + rr) & 3) * 4;
            const int o1 = ((1 + rr) & 3) * 4;
            const int o2 = ((2 + rr) & 3) * 4;
            const int o3 = ((3 + rr) & 3) * 4;
            #pragma unroll
            for (int b = 0; b < 8; b++) {
                const int k = a * 8 + b;
                const float* row = Xm + k * XSTR;
                ulonglong2 q0 = *(const ulonglong2*)(row + o0);
                ulonglong2 q1 = *(const ulonglong2*)(row + o1);
                ulonglong2 q2 = *(const ulonglong2*)(row + o2);
                ulonglong2 q3 = *(const ulonglong2*)(row + o3);
                unsigned long long wp = *(const unsigned long long*)(We2s + k * 64 + j0);
                ffma2(acc[0], q0.x, wp); ffma2(acc[1], q0.y, wp);
                ffma2(acc[2], q1.x, wp); ffma2(acc[3], q1.y, wp);
                ffma2(acc[4], q2.x, wp); ffma2(acc[5], q2.y, wp);
                ffma2(acc[6], q3.x, wp); ffma2(acc[7], q3.y, wp);
            }
        }
        __syncwarp();   // everyone done reading m before overwrite with em
        // em[e] = edge e's (col j0, col j0+1) — kept in regs for the scatter.
        unsigned long long em[EB];
        #pragma unroll
        for (int p = 0; p < 4; p++) {
            float l0, h0, l1, h1;
            unpack2(acc[2 * p], l0, h0);       // edge 2p:   l0=col j0, h0=col j0+1
            unpack2(acc[2 * p + 1], l1, h1);   // edge 2p+1: l1=col j0, h1=col j0+1
            l0 = silu(l0); h0 = silu(h0); l1 = silu(l1); h1 = silu(h1);
            em[2 * p]     = pack2(l0, h0);
            em[2 * p + 1] = pack2(l1, h1);
            *(float4*)st0[p] = make_float4(l0, l0, l1, l1);
            *(float4*)st1[p] = make_float4(h0, h0, h1, h1);
        }
        __syncwarp();

        // ---- coord MLP layer 1: (64 -> 64), SiLU
        unsigned long long acc3[EB];
        #pragma unroll
        for (int e = 0; e < EB; e++) acc3[e] = bc1p;
        #pragma unroll 1
        for (int a = 0; a < 8; a++) {
            const int rr = a & 3;
            const int o0 = ((0 + rr) & 3) * 4;
            const int o1 = ((1 + rr) & 3) * 4;
            const int o2 = ((2 + rr) & 3) * 4;
            const int o3 = ((3 + rr) & 3) * 4;
            #pragma unroll
            for (int b = 0; b < 8; b++) {
                const int k = a * 8 + b;
                const float* row = Xm + k * XSTR;
                ulonglong2 q0 = *(const ulonglong2*)(row + o0);
                ulonglong2 q1 = *(const ulonglong2*)(row + o1);
                ulonglong2 q2 = *(const ulonglong2*)(row + o2);
                ulonglong2 q3 = *(const ulonglong2*)(row + o3);
                unsigned long long wp = *(const unsigned long long*)(Wc1s + k * 64 + j0);
                ffma2(acc3[0], q0.x, wp); ffma2(acc3[1], q0.y, wp);
                ffma2(acc3[2], q1.x, wp); ffma2(acc3[3], q1.y, wp);
                ffma2(acc3[4], q2.x, wp); ffma2(acc3[5], q2.y, wp);
                ffma2(acc3[6], q3.x, wp); ffma2(acc3[7], q3.y, wp);
            }
        }
        // ---- coord MLP layer 2: (64 -> 1), warp reduction per edge
        #pragma unroll
        for (int e = 0; e < EB; e++) {
            float lo, hi; unpack2(acc3[e], lo, hi);
            float v = fmaf(silu(lo), wc2_0, silu(hi) * wc2_1);
            v += __shfl_xor_sync(0xffffffffu, v, 16);
            v += __shfl_xor_sync(0xffffffffu, v, 8);
            v += __shfl_xor_sync(0xffffffffu, v, 4);
            v += __shfl_xor_sync(0xffffffffu, v, 2);
            v += __shfl_xor_sync(0xffffffffu, v, 1);
            if (lane == 0) cwS[e] = v + bc2v;
        }
        __syncwarp();

        // ---- scatter: one vector RED per lane per edge (em from regs)
        #pragma unroll
        for (int e = 0; e < EB; e++) {
            float lo, hi; unpack2(em[e], lo, hi);
            red_add_v2(g_msg + (size_t)idx[e] * 64 + j0, lo, hi);
        }
        if (lane < 24) {
            const int e = lane / 3;
            const int c = lane - e * 3;
            atomicAdd(g_coord + (size_t)idx[e] * 3 + c, rl[lane] * cwS[e]);
        }
    }
}

// ---------------------------------------------------------------------------
// Node kernel: warp per 4 nodes; occupancy raised to 3 CTAs/SM.
// ---------------------------------------------------------------------------
__global__ __launch_bounds__(256, 3) void node_kernel(
    const float* __restrict__ h, const float* __restrict__ pos,
    const float* __restrict__ Wn1, const float* __restrict__ bn1,
    const float* __restrict__ Wn2, const float* __restrict__ bn2,
    float* __restrict__ hout, float* __restrict__ posout)
{
    extern __shared__ float sm[];
    float* Wn1s = sm;
    float* Wn2s = Wn1s + 128 * 64;
    float* bn1s = Wn2s + 64 * 64;
    float* bn2s = bn1s + 64;
    float* scr  = bn2s + 64;

    const int tid = threadIdx.x;
    for (int i = tid; i < 128 * 64; i += 256) Wn1s[i] = Wn1[i];
    for (int i = tid; i < 64 * 64; i += 256) Wn2s[i] = Wn2[i];
    if (tid < 64) { bn1s[tid] = bn1[tid]; bn2s[tid] = bn2[tid]; }
    __syncthreads();

    const int lane = tid & 31;
    const int w = tid >> 5;
    const int j0 = lane * 2;
    float* X = scr + w * 512;

    const int nTiles = N_NODES / 4;
    const int warpStride = gridDim.x * 8;

    for (int t = blockIdx.x * 8 + w; t < nTiles; t += warpStride) {
        __syncwarp();
        const int base = t * 4;
        #pragma unroll
        for (int e = 0; e < 4; e++) {
            const int n = base + e;
            ((float2*)(X + e * 128))[lane]      = ((const float2*)(h + (size_t)n * 64))[lane];
            ((float2*)(X + e * 128 + 64))[lane] = ((const float2*)(g_msg + (size_t)n * 64))[lane];
        }
        __syncwarp();

        float acc[4][2];
        {
            float b0 = bn1s[j0], b1 = bn1s[j0 + 1];
            #pragma unroll
            for (int e = 0; e < 4; e++) { acc[e][0] = b0; acc[e][1] = b1; }
        }
        #pragma unroll 2
        for (int k = 0; k < 128; k += 4) {
            float xv[4][4];
            #pragma unroll
            for (int e = 0; e < 4; e++) {
                float4 q = *(const float4*)(X + e * 128 + k);
                xv[e][0] = q.x; xv[e][1] = q.y; xv[e][2] = q.z; xv[e][3] = q.w;
            }
            #pragma unroll
            for (int kk = 0; kk < 4; kk++) {
                float2 wv = *(const float2*)(Wn1s + (k + kk) * 64 + j0);
                #pragma unroll
                for (int e = 0; e < 4; e++) {
                    acc[e][0] = fmaf(xv[e][kk], wv.x, acc[e][0]);
                    acc[e][1] = fmaf(xv[e][kk], wv.y, acc[e][1]);
                }
            }
        }
        __syncwarp();
        #pragma unroll
        for (int e = 0; e < 4; e++) {
            *(float2*)(X + e * 64 + j0) =
                make_float2(silu(acc[e][0]), silu(acc[e][1]));
        }
        __syncwarp();

        float acc2[4][2];
        {
            float b0 = bn2s[j0], b1 = bn2s[j0 + 1];
            #pragma unroll
            for (int e = 0; e < 4; e++) { acc2[e][0] = b0; acc2[e][1] = b1; }
        }
        #pragma unroll 2
        for (int k = 0; k < 64; k += 4) {
            float xv[4][4];
            #pragma unroll
            for (int e = 0; e < 4; e++) {
                float4 q = *(const float4*)(X + e * 64 + k);
                xv[e][0] = q.x; xv[e][1] = q.y; xv[e][2] = q.z; xv[e][3] = q.w;
            }
            #pragma unroll
            for (int kk = 0; kk < 4; kk++) {
                float2 wv = *(const float2*)(Wn2s + (k + kk) * 64 + j0);
                #pragma unroll
                for (int e = 0; e < 4; e++) {
                    acc2[e][0] = fmaf(xv[e][kk], wv.x, acc2[e][0]);
                    acc2[e][1] = fmaf(xv[e][kk], wv.y, acc2[e][1]);
                }
            }
        }
        #pragma unroll
        for (int e = 0; e < 4; e++) {
            const int n = base + e;
            ((float2*)(hout + (size_t)n * 64))[lane] =
                make_float2(acc2[e][0], acc2[e][1]);
        }
        if (lane < 12) {
            const int e = lane / 3;
            const int c = lane - e * 3;
            const int n = base + e;
            posout[n * 3 + c] = pos[n * 3 + c] + g_coord[n * 3 + c];
        }
    }
}

// ---------------------------------------------------------------------------
extern "C" void kernel_launch(void* const* d_in, const int* in_sizes, int n_in,
                              void* d_out, int out_size)
{
    const float* h   = (const float*)d_in[0];
    const float* pos = (const float*)d_in[1];
    const unsigned int* ei_words = (const unsigned int*)d_in[2];
    const float* We1 = (const float*)d_in[3];
    const float* be1 = (const float*)d_in[4];
    const float* We2 = (const float*)d_in[5];
    const float* be2 = (const float*)d_in[6];
    const float* Wc1 = (const float*)d_in[7];
    const float* bc1 = (const float*)d_in[8];
    const float* Wc2 = (const float*)d_in[9];
    const float* bc2 = (const float*)d_in[10];
    const float* Wn1 = (const float*)d_in[11];
    const float* bn1 = (const float*)d_in[12];
    const float* Wn2 = (const float*)d_in[13];
    const float* bn2 = (const float*)d_in[14];

    float* hout   = (float*)d_out;
    float* posout = hout + (size_t)N_NODES * 64;

    void* msgPtr = nullptr;
    void* coordPtr = nullptr;
    cudaGetSymbolAddress(&msgPtr, g_msg);
    cudaGetSymbolAddress(&coordPtr, g_coord);
    cudaMemsetAsync(msgPtr, 0, sizeof(float) * (size_t)N_NODES * 64);
    cudaMemsetAsync(coordPtr, 0, sizeof(float) * (size_t)N_NODES * 3);

    align_dummy<<<1, 32>>>();
    decode_edges<<<1024, 256>>>(ei_words);

    const int PROJ_SMEM = (128 * 64 + 8 * 256) * 4;
    const int EDGE_SMEM = (2 * 64 * 64 + 5 * 64 + EWARPS * WSCR) * 4;
    const int NODE_SMEM = (128 * 64 + 64 * 64 + 2 * 64 + 8 * 512) * 4;

    cudaFuncSetAttribute(proj_kernel, cudaFuncAttributeMaxDynamicSharedMemorySize, PROJ_SMEM);
    cudaFuncSetAttribute(edge_kernel, cudaFuncAttributeMaxDynamicSharedMemorySize, EDGE_SMEM);
    cudaFuncSetAttribute(node_kernel, cudaFuncAttributeMaxDynamicSharedMemorySize, NODE_SMEM);

    proj_kernel<<<304, 256, PROJ_SMEM>>>(h, We1);
    edge_kernel<<<148, EWARPS * 32, EDGE_SMEM>>>(pos,
                                                 We1, be1, We2, be2,
                                                 Wc1, bc1, Wc2, bc2);
    node_kernel<<<444, 256, NODE_SMEM>>>(h, pos, Wn1, bn1, Wn2, bn2,
                                         hout, posout);
}